// round 13
// baseline (speedup 1.0000x reference)
#include <cuda_runtime.h>
#include <cuda_fp16.h>
#include <cstdint>
#include <cstddef>

#define NU_MAX 100000
#define NB_MAX 50000
#define E_MAX  2000000
#define C 64
#define H 128

// ---------------- device scratch (static, allocation-free) -----------
__device__ float g_u0[NU_MAX * C];
__device__ float g_b0[NB_MAX * C];
__device__ float g_u1[NU_MAX * C];
__device__ float g_b1[NB_MAX * C];
__device__ float g_u2[NU_MAX * C];
__device__ float g_b2[NB_MAX * C];
__device__ float g_mu[NU_MAX * C];
__device__ float g_mb[NB_MAX * C];
__device__ __half g_u0h[NU_MAX * C];
__device__ __half g_b0h[NB_MAX * C];
__device__ __half g_u1h[NU_MAX * C];
__device__ __half g_b1h[NB_MAX * C];
__device__ __half g_uph[NU_MAX * H];
__device__ __half g_bph[NB_MAX * H];
// CSR structures
__device__ int g_deg_u[NU_MAX];
__device__ int g_deg_b[NB_MAX];
__device__ int g_off_u[NU_MAX];
__device__ int g_off_b[NB_MAX];
__device__ int g_pos_u[E_MAX];
__device__ int g_pos_b[E_MAX];
__device__ int g_nbr_b_of_u[E_MAX];
__device__ int g_nbr_u_of_b[E_MAX];
__device__ int g_counters[2];
__device__ int g_bar[2];          // spin-barrier counters (zeroed each call)

static __device__ __forceinline__ uint2 pack_half4(float a, float b, float c, float d) {
    __half2 h01 = __floats2half2_rn(a, b);
    __half2 h23 = __floats2half2_rn(c, d);
    uint2 r;
    r.x = *reinterpret_cast<unsigned*>(&h01);
    r.y = *reinterpret_cast<unsigned*>(&h23);
    return r;
}

// ---------------- launch 1: zero everything the CSR build needs ----------------
__global__ void zero_all_kernel(int* __restrict__ a, int na,
                                int* __restrict__ b, int nb_,
                                int* __restrict__ c, int nc,
                                int* __restrict__ d, int nd) {
    int i = blockIdx.x * blockDim.x + threadIdx.x;
    if (i < na) a[i] = 0;
    if (i < nb_) b[i] = 0;
    if (i < nc) c[i] = 0;
    if (i < nd) d[i] = 0;
}

// ---------------- launch 2: fused CSR build (one persistent kernel) -------------
// 128 blocks x 1024 threads, all co-resident; one-shot spin barriers.
#define CSR_BLOCKS 128
static __device__ __forceinline__ void grid_barrier(int* cnt) {
    __syncthreads();
    if (threadIdx.x == 0) {
        __threadfence();
        atomicAdd(cnt, 1);
        while (atomicAdd(cnt, 0) < CSR_BLOCKS) __nanosleep(64);
        __threadfence();
    }
    __syncthreads();
}

__global__ void __launch_bounds__(1024, 1)
csr_build_kernel(const int* __restrict__ src, const int* __restrict__ dst,
                 int* __restrict__ degu, int* __restrict__ degb,
                 int* __restrict__ posu, int* __restrict__ posb,
                 int* __restrict__ offu, int* __restrict__ offb,
                 int* __restrict__ nbr_b_of_u, int* __restrict__ nbr_u_of_b,
                 int* __restrict__ counters, int* __restrict__ bar,
                 int nu, int nb, int E) {
    int tid = threadIdx.x, lane = tid & 31, wid = tid >> 5;
    int gthreads = CSR_BLOCKS * 1024;
    int gtid0 = blockIdx.x * 1024 + tid;

    // ---- phase 1: degree + per-edge positions ----
    int nchunk4 = E >> 2;            // full int4 chunks
    for (int t = gtid0; t < nchunk4; t += gthreads) {
        int4 s4 = __ldg(reinterpret_cast<const int4*>(src) + t);
        int4 d4 = __ldg(reinterpret_cast<const int4*>(dst) + t);
        int4 pu, pb;
        pu.x = atomicAdd(degu + s4.x, 1);
        pu.y = atomicAdd(degu + s4.y, 1);
        pu.z = atomicAdd(degu + s4.z, 1);
        pu.w = atomicAdd(degu + s4.w, 1);
        pb.x = atomicAdd(degb + d4.x, 1);
        pb.y = atomicAdd(degb + d4.y, 1);
        pb.z = atomicAdd(degb + d4.z, 1);
        pb.w = atomicAdd(degb + d4.w, 1);
        reinterpret_cast<int4*>(posu)[t] = pu;
        reinterpret_cast<int4*>(posb)[t] = pb;
    }
    if (gtid0 == 0) {
        for (int i = nchunk4 * 4; i < E; i++) {
            posu[i] = atomicAdd(degu + __ldg(src + i), 1);
            posb[i] = atomicAdd(degb + __ldg(dst + i), 1);
        }
    }
    grid_barrier(bar + 0);

    // ---- phase 2: offsets via block-chunk scan + atomic base ----
    __shared__ int s_warp[32];
    __shared__ int s_base;
    int cu = (nu + 1023) >> 10;          // user chunks
    int cb = (nb + 1023) >> 10;
    int ctot = cu + cb;
    for (int ch = blockIdx.x; ch < ctot; ch += CSR_BLOCKS) {
        bool isU = ch < cu;
        const int* deg = isU ? degu : degb;
        int* off = isU ? offu : offb;
        int* counter = counters + (isU ? 0 : 1);
        int n = isU ? nu : nb;
        int cid = isU ? ch : ch - cu;
        int i = cid * 1024 + tid;
        int v = (i < n) ? deg[i] : 0;
        int x = v;
        #pragma unroll
        for (int o = 1; o < 32; o <<= 1) {
            int t = __shfl_up_sync(0xFFFFFFFFu, x, o);
            if (lane >= o) x += t;
        }
        if (lane == 31) s_warp[wid] = x;
        __syncthreads();
        if (wid == 0) {
            int w = s_warp[lane];
            #pragma unroll
            for (int o = 1; o < 32; o <<= 1) {
                int t = __shfl_up_sync(0xFFFFFFFFu, w, o);
                if (lane >= o) w += t;
            }
            s_warp[lane] = w;
        }
        __syncthreads();
        if (tid == 0) s_base = atomicAdd(counter, s_warp[31]);
        __syncthreads();
        int warpoff = (wid == 0) ? 0 : s_warp[wid - 1];
        if (i < n) off[i] = s_base + warpoff + x - v;
        __syncthreads();
    }
    grid_barrier(bar + 1);

    // ---- phase 3: atomic-free scatter ----
    for (int t = gtid0; t < nchunk4; t += gthreads) {
        int4 s4 = __ldg(reinterpret_cast<const int4*>(src) + t);
        int4 d4 = __ldg(reinterpret_cast<const int4*>(dst) + t);
        int4 pu = reinterpret_cast<const int4*>(posu)[t];
        int4 pb = reinterpret_cast<const int4*>(posb)[t];
        nbr_b_of_u[__ldg(offu + s4.x) + pu.x] = d4.x;
        nbr_b_of_u[__ldg(offu + s4.y) + pu.y] = d4.y;
        nbr_b_of_u[__ldg(offu + s4.z) + pu.z] = d4.z;
        nbr_b_of_u[__ldg(offu + s4.w) + pu.w] = d4.w;
        nbr_u_of_b[__ldg(offb + d4.x) + pb.x] = s4.x;
        nbr_u_of_b[__ldg(offb + d4.y) + pb.y] = s4.y;
        nbr_u_of_b[__ldg(offb + d4.z) + pb.z] = s4.z;
        nbr_u_of_b[__ldg(offb + d4.w) + pb.w] = s4.w;
    }
    if (gtid0 == 0) {
        for (int i = nchunk4 * 4; i < E; i++) {
            int s = __ldg(src + i), d = __ldg(dst + i);
            nbr_b_of_u[__ldg(offu + s) + posu[i]] = d;
            nbr_u_of_b[__ldg(offb + d) + posb[i]] = s;
        }
    }
}

// ---------------- launch 3: fused projections (user elementwise + book staged GEMM) --
// dynamic smem (book part): s_w[96*64] | s_a[64*104] | s_bias[64]
#define PROJ_SMEM ((96 * 64 + 64 * 104 + 64) * 4)
__global__ void __launch_bounds__(256)
proj2_kernel(const float* __restrict__ ux, const float* __restrict__ uw,
             const float* __restrict__ ub, float* __restrict__ uout,
             __half* __restrict__ uouth, int nu,
             const float* __restrict__ bx, const float* __restrict__ bw,
             const float* __restrict__ bb, float* __restrict__ bout,
             __half* __restrict__ bouth, int nb, int ublocks) {
    if ((int)blockIdx.x < ublocks) {
        // user part: 16 threads per node, 4 channels each
        unsigned i = blockIdx.x * 256 + threadIdx.x;
        if (i >= (unsigned)nu * 16u) return;
        unsigned node = i >> 4, j4 = (i & 15u) * 4;
        const float* xr = ux + (size_t)node * 3;
        float x0 = __ldg(xr), x1 = __ldg(xr + 1), x2 = __ldg(xr + 2);
        float4 bbv = __ldg(reinterpret_cast<const float4*>(ub + j4));
        float4 w0 = __ldg(reinterpret_cast<const float4*>(uw + j4));
        float4 w1 = __ldg(reinterpret_cast<const float4*>(uw + 64 + j4));
        float4 w2 = __ldg(reinterpret_cast<const float4*>(uw + 128 + j4));
        float4 r;
        r.x = bbv.x + x0 * w0.x + x1 * w1.x + x2 * w2.x;
        r.y = bbv.y + x0 * w0.y + x1 * w1.y + x2 * w2.y;
        r.z = bbv.z + x0 * w0.z + x1 * w1.z + x2 * w2.z;
        r.w = bbv.w + x0 * w0.w + x1 * w1.w + x2 * w2.w;
        *reinterpret_cast<float4*>(uout + (size_t)node * 64 + j4) = r;
        *reinterpret_cast<uint2*>(uouth + (size_t)node * 64 + j4) = pack_half4(r.x, r.y, r.z, r.w);
        return;
    }
    // book part: staged K-chunked GEMM [64 nodes x 384] @ [384 x 64]
    extern __shared__ __align__(16) float dyn[];
    float* s_w = dyn;                   // 96*64
    float* s_a = dyn + 96 * 64;         // 64*104
    float* s_bias = s_a + 64 * 104;     // 64
    int tid = threadIdx.x;
    if (tid < 64) s_bias[tid] = bb[tid];
    int bid = blockIdx.x - ublocks;
    int gsz = gridDim.x - ublocks;
    int ty = tid >> 4, tx = tid & 15;
    int row = tid >> 2, seg = tid & 3;

    for (int tile = bid * 64; tile < nb; tile += gsz * 64) {
        float4 c[4];
        #pragma unroll
        for (int i = 0; i < 4; i++)
            c[i] = make_float4(0.f, 0.f, 0.f, 0.f);
        for (int ch = 0; ch < 4; ch++) {
            __syncthreads();
            // stage weight chunk [96 x 64]
            for (int i = tid; i < 96 * 64 / 4; i += 256)
                reinterpret_cast<float4*>(s_w)[i] =
                    __ldg(reinterpret_cast<const float4*>(bw + ch * 96 * 64) + i);
            // stage A chunk [64 nodes x 96]
            {
                int node = tile + row;
                float* dstp = s_a + row * 104 + seg * 24;
                if (node < nb) {
                    const float4* srcp = reinterpret_cast<const float4*>(
                        bx + (size_t)node * 384 + ch * 96 + seg * 24);
                    #pragma unroll
                    for (int q = 0; q < 6; q++)
                        reinterpret_cast<float4*>(dstp)[q] = __ldg(srcp + q);
                } else {
                    #pragma unroll
                    for (int q = 0; q < 6; q++)
                        reinterpret_cast<float4*>(dstp)[q] = make_float4(0.f, 0.f, 0.f, 0.f);
                }
            }
            __syncthreads();
            const float* a0p = s_a + (ty * 4 + 0) * 104;
            const float* a1p = s_a + (ty * 4 + 1) * 104;
            const float* a2p = s_a + (ty * 4 + 2) * 104;
            const float* a3p = s_a + (ty * 4 + 3) * 104;
            #pragma unroll 4
            for (int k = 0; k < 96; k++) {
                float4 w = *reinterpret_cast<const float4*>(s_w + k * 64 + tx * 4);
                float a0 = a0p[k], a1 = a1p[k], a2 = a2p[k], a3 = a3p[k];
                c[0].x += a0 * w.x; c[0].y += a0 * w.y; c[0].z += a0 * w.z; c[0].w += a0 * w.w;
                c[1].x += a1 * w.x; c[1].y += a1 * w.y; c[1].z += a1 * w.z; c[1].w += a1 * w.w;
                c[2].x += a2 * w.x; c[2].y += a2 * w.y; c[2].z += a2 * w.z; c[2].w += a2 * w.w;
                c[3].x += a3 * w.x; c[3].y += a3 * w.y; c[3].z += a3 * w.z; c[3].w += a3 * w.w;
            }
        }
        float4 bv = *reinterpret_cast<const float4*>(s_bias + tx * 4);
        #pragma unroll
        for (int i = 0; i < 4; i++) {
            int nd = tile + ty * 4 + i;
            if (nd < nb) {
                float4 r;
                r.x = c[i].x + bv.x; r.y = c[i].y + bv.y;
                r.z = c[i].z + bv.z; r.w = c[i].w + bv.w;
                *reinterpret_cast<float4*>(bout + (size_t)nd * 64 + tx * 4) = r;
                *reinterpret_cast<uint2*>(bouth + (size_t)nd * 64 + tx * 4) =
                    pack_half4(r.x, r.y, r.z, r.w);
            }
        }
    }
}

// ---------------- gather helpers ----------------
static __device__ __forceinline__ void addrow8(float* a, uint4 v) {
    float2 p0 = __half22float2(*reinterpret_cast<const __half2*>(&v.x));
    float2 p1 = __half22float2(*reinterpret_cast<const __half2*>(&v.y));
    float2 p2 = __half22float2(*reinterpret_cast<const __half2*>(&v.z));
    float2 p3 = __half22float2(*reinterpret_cast<const __half2*>(&v.w));
    a[0] += p0.x; a[1] += p0.y; a[2] += p1.x; a[3] += p1.y;
    a[4] += p2.x; a[5] += p2.y; a[6] += p3.x; a[7] += p3.y;
}

// ---------------- launch 4: fused dual-side sage gather (PROFILED) ----------------
__global__ void __launch_bounds__(256)
sage_gather2_kernel(const __half* __restrict__ xA, const int* __restrict__ offA,
                    const int* __restrict__ degA, const int* __restrict__ nbrA,
                    float* __restrict__ mA, int nA,
                    const __half* __restrict__ xB, const int* __restrict__ offB,
                    const int* __restrict__ degB, const int* __restrict__ nbrB,
                    float* __restrict__ mB, int nB,
                    int gsplit) {
    const unsigned FULL = 0xFFFFFFFFu;
    const __half* xsrc;
    const int *offs, *degs, *nbr;
    float* mout;
    int n, bid, gsz;
    if ((int)blockIdx.x < gsplit) {
        xsrc = xA; offs = offA; degs = degA; nbr = nbrA; mout = mA; n = nA;
        bid = blockIdx.x; gsz = gsplit;
    } else {
        xsrc = xB; offs = offB; degs = degB; nbr = nbrB; mout = mB; n = nB;
        bid = blockIdx.x - gsplit; gsz = gridDim.x - gsplit;
    }
    int lane = threadIdx.x & 31, wid = threadIdx.x >> 5;
    int lane8 = lane & 7, quad = lane >> 3;

    for (int base = bid * 32 + wid * 4; base < n; base += gsz * 32) {
        int node = base + quad;
        bool valid = node < n;
        int beg = 0, dg = 0;
        if (valid) { beg = __ldg(offs + node); dg = __ldg(degs + node); }
        int nbq = (dg + 7) >> 3;
        int m1 = max(nbq, __shfl_xor_sync(FULL, nbq, 8));
        int nbatch = max(m1, __shfl_xor_sync(FULL, m1, 16));

        float accA[8] = {0.f, 0.f, 0.f, 0.f, 0.f, 0.f, 0.f, 0.f};
        float accB[8] = {0.f, 0.f, 0.f, 0.f, 0.f, 0.f, 0.f, 0.f};

        int sidx = (lane8 < dg) ? __ldg(nbr + beg + lane8) : 0;
        for (int b = 0; b < nbatch; b++) {
            int rem = dg - b * 8;
            int sidx_next = 0;
            if (b + 1 < nbatch) {
                int rem2 = dg - (b + 1) * 8;
                sidx_next = (lane8 < rem2) ? __ldg(nbr + beg + (b + 1) * 8 + lane8) : 0;
            }
            uint4 r[8];
            #pragma unroll
            for (int j = 0; j < 8; j++) {
                int s = __shfl_sync(FULL, sidx, j, 8);
                r[j] = __ldg(reinterpret_cast<const uint4*>(xsrc + (size_t)s * 64) + lane8);
            }
            #pragma unroll
            for (int j = 0; j < 8; j += 2) {
                if (j < rem)     addrow8(accA, r[j]);
                if (j + 1 < rem) addrow8(accB, r[j + 1]);
            }
            sidx = sidx_next;
        }
        if (valid) {
            float inv = 1.0f / fmaxf((float)dg, 1.0f);
            float4 m0, m1v;
            m0.x = (accA[0] + accB[0]) * inv;
            m0.y = (accA[1] + accB[1]) * inv;
            m0.z = (accA[2] + accB[2]) * inv;
            m0.w = (accA[3] + accB[3]) * inv;
            m1v.x = (accA[4] + accB[4]) * inv;
            m1v.y = (accA[5] + accB[5]) * inv;
            m1v.z = (accA[6] + accB[6]) * inv;
            m1v.w = (accA[7] + accB[7]) * inv;
            float4* dst = reinterpret_cast<float4*>(mout + (size_t)node * 64 + lane8 * 8);
            dst[0] = m0;
            dst[1] = m1v;
        }
    }
}

// ---------------- fused dual-side sage transform: staged 64-node GEMM ----------------
#define SAGE_T_SMEM ((128 * 64 + 64 * 132 + 64) * 4)
template <bool RELU, bool EMIT_H>
__global__ void __launch_bounds__(256)
sage_transform2_kernel(const float* __restrict__ MA, const float* __restrict__ XA,
                       const float* __restrict__ wlA, const float* __restrict__ biasA,
                       const float* __restrict__ wrA,
                       float* __restrict__ outA, __half* __restrict__ outhA, int nA,
                       const float* __restrict__ MB, const float* __restrict__ XB,
                       const float* __restrict__ wlB, const float* __restrict__ biasB,
                       const float* __restrict__ wrB,
                       float* __restrict__ outB, __half* __restrict__ outhB, int nB,
                       int gsplit) {
    extern __shared__ __align__(16) float dyn[];
    float* s_w = dyn;                      // 128*64
    float* s_a = dyn + 128 * 64;           // 64*132
    float* s_bias = s_a + 64 * 132;        // 64

    const float *M, *X, *wl, *bias, *wr;
    float* out;
    __half* outh;
    int n, bid, gsz;
    if ((int)blockIdx.x < gsplit) {
        M = MA; X = XA; wl = wlA; bias = biasA; wr = wrA; out = outA; outh = outhA; n = nA;
        bid = blockIdx.x; gsz = gsplit;
    } else {
        M = MB; X = XB; wl = wlB; bias = biasB; wr = wrB; out = outB; outh = outhB; n = nB;
        bid = blockIdx.x - gsplit; gsz = gridDim.x - gsplit;
    }
    int tid = threadIdx.x;
    for (int i = tid; i < 64 * 64; i += 256) { s_w[i] = wl[i]; s_w[4096 + i] = wr[i]; }
    if (tid < 64) s_bias[tid] = bias[tid];
    int ty = tid >> 4, tx = tid & 15;
    int row = tid >> 2, seg = tid & 3;

    for (int tile = bid * 64; tile < n; tile += gsz * 64) {
        __syncthreads();
        {
            int node = tile + row;
            float* dstp = s_a + row * 132 + seg * 32;
            if (node < n) {
                const float* srcp = (seg < 2) ? (M + (size_t)node * 64 + seg * 32)
                                              : (X + (size_t)node * 64 + (seg - 2) * 32);
                #pragma unroll
                for (int q = 0; q < 8; q++)
                    reinterpret_cast<float4*>(dstp)[q] =
                        __ldg(reinterpret_cast<const float4*>(srcp) + q);
            } else {
                #pragma unroll
                for (int q = 0; q < 8; q++)
                    reinterpret_cast<float4*>(dstp)[q] = make_float4(0.f, 0.f, 0.f, 0.f);
            }
        }
        __syncthreads();
        float4 c0 = *reinterpret_cast<const float4*>(s_bias + tx * 4);
        float4 c1 = c0, c2 = c0, c3 = c0;
        const float* a0p = s_a + (ty * 4 + 0) * 132;
        const float* a1p = s_a + (ty * 4 + 1) * 132;
        const float* a2p = s_a + (ty * 4 + 2) * 132;
        const float* a3p = s_a + (ty * 4 + 3) * 132;
        #pragma unroll 4
        for (int k = 0; k < 128; k++) {
            float4 w = *reinterpret_cast<const float4*>(s_w + k * 64 + tx * 4);
            float a0 = a0p[k], a1 = a1p[k], a2 = a2p[k], a3 = a3p[k];
            c0.x += a0 * w.x; c0.y += a0 * w.y; c0.z += a0 * w.z; c0.w += a0 * w.w;
            c1.x += a1 * w.x; c1.y += a1 * w.y; c1.z += a1 * w.z; c1.w += a1 * w.w;
            c2.x += a2 * w.x; c2.y += a2 * w.y; c2.z += a2 * w.z; c2.w += a2 * w.w;
            c3.x += a3 * w.x; c3.y += a3 * w.y; c3.z += a3 * w.z; c3.w += a3 * w.w;
        }
        if (RELU) {
            c0.x = fmaxf(c0.x, 0.f); c0.y = fmaxf(c0.y, 0.f); c0.z = fmaxf(c0.z, 0.f); c0.w = fmaxf(c0.w, 0.f);
            c1.x = fmaxf(c1.x, 0.f); c1.y = fmaxf(c1.y, 0.f); c1.z = fmaxf(c1.z, 0.f); c1.w = fmaxf(c1.w, 0.f);
            c2.x = fmaxf(c2.x, 0.f); c2.y = fmaxf(c2.y, 0.f); c2.z = fmaxf(c2.z, 0.f); c2.w = fmaxf(c2.w, 0.f);
            c3.x = fmaxf(c3.x, 0.f); c3.y = fmaxf(c3.y, 0.f); c3.z = fmaxf(c3.z, 0.f); c3.w = fmaxf(c3.w, 0.f);
        }
        float4 cc[4] = {c0, c1, c2, c3};
        #pragma unroll
        for (int i = 0; i < 4; i++) {
            int nd = tile + ty * 4 + i;
            if (nd < n) {
                *reinterpret_cast<float4*>(out + (size_t)nd * 64 + tx * 4) = cc[i];
                if (EMIT_H)
                    *reinterpret_cast<uint2*>(outh + (size_t)nd * 64 + tx * 4) =
                        pack_half4(cc[i].x, cc[i].y, cc[i].z, cc[i].w);
            }
        }
    }
}

// ---------------- fused dual-side decoder precompute: staged GEMM --------------------
#define DEC_P_SMEM ((64 * 128 + 64 * 68 + 128) * 4)
__global__ void __launch_bounds__(256)
dec_pre2_kernel(const float* __restrict__ xA, const float* __restrict__ wA,
                const float* __restrict__ biasA, __half* __restrict__ outA, int nA,
                const float* __restrict__ xB, const float* __restrict__ wB,
                __half* __restrict__ outB, int nB, int gsplit) {
    extern __shared__ __align__(16) float dyn[];
    float* s_w = dyn;                      // 64*128
    float* s_a = dyn + 64 * 128;           // 64*68
    float* s_bias = s_a + 64 * 68;         // 128

    const float *x, *w, *bias;
    __half* out;
    int n, bid, gsz;
    if ((int)blockIdx.x < gsplit) {
        x = xA; w = wA; bias = biasA; out = outA; n = nA;
        bid = blockIdx.x; gsz = gsplit;
    } else {
        x = xB; w = wB; bias = nullptr; out = outB; n = nB;
        bid = blockIdx.x - gsplit; gsz = gridDim.x - gsplit;
    }
    int tid = threadIdx.x;
    for (int i = tid; i < 64 * 128; i += 256) s_w[i] = w[i];
    if (tid < 128) s_bias[tid] = bias ? bias[tid] : 0.f;
    int ty = tid >> 5, tx = tid & 31;
    int row = tid >> 2, seg = tid & 3;

    for (int tile = bid * 64; tile < n; tile += gsz * 64) {
        __syncthreads();
        {
            int node = tile + row;
            float* dstp = s_a + row * 68 + seg * 16;
            if (node < n) {
                const float4* srcp = reinterpret_cast<const float4*>(x + (size_t)node * 64 + seg * 16);
                #pragma unroll
                for (int q = 0; q < 4; q++)
                    reinterpret_cast<float4*>(dstp)[q] = __ldg(srcp + q);
            } else {
                #pragma unroll
                for (int q = 0; q < 4; q++)
                    reinterpret_cast<float4*>(dstp)[q] = make_float4(0.f, 0.f, 0.f, 0.f);
            }
        }
        __syncthreads();
        float4 b4 = *reinterpret_cast<const float4*>(s_bias + tx * 4);
        float4 c[8];
        #pragma unroll
        for (int i = 0; i < 8; i++) c[i] = b4;
        #pragma unroll 2
        for (int k = 0; k < 64; k++) {
            float4 w4 = *reinterpret_cast<const float4*>(s_w + k * 128 + tx * 4);
            #pragma unroll
            for (int i = 0; i < 8; i++) {
                float a = s_a[(ty * 8 + i) * 68 + k];
                c[i].x += a * w4.x; c[i].y += a * w4.y; c[i].z += a * w4.z; c[i].w += a * w4.w;
            }
        }
        #pragma unroll
        for (int i = 0; i < 8; i++) {
            int nd = tile + ty * 8 + i;
            if (nd < n)
                *reinterpret_cast<uint2*>(out + (size_t)nd * 128 + tx * 4) =
                    pack_half4(c[i].x, c[i].y, c[i].z, c[i].w);
        }
    }
}

// ---------------- decoder edge kernel: half-warp per edge, uint4 fp16 loads ----------
__global__ void __launch_bounds__(256)
dec_edge_kernel(const __half* __restrict__ Up, const __half* __restrict__ Bp,
                const int* __restrict__ ls, const int* __restrict__ ld,
                const float* __restrict__ w2, const float* __restrict__ b2,
                float* __restrict__ out, int m) {
    __shared__ float s_w2[128];
    if (threadIdx.x < 128) s_w2[threadIdx.x] = w2[threadIdx.x];
    __syncthreads();
    const unsigned FULL = 0xFFFFFFFFu;
    int lane = threadIdx.x & 31, wid = threadIdx.x >> 5;
    int lane16 = lane & 15, half = lane >> 4;
    float bb = __ldg(b2);
    float wv[8];
    #pragma unroll
    for (int i = 0; i < 8; i++) wv[i] = s_w2[lane16 * 8 + i];

    int ghalf = (blockIdx.x * 8 + wid) * 2 + half;
    int stride = gridDim.x * 16;
    for (int e0 = ghalf * 2; e0 < m; e0 += stride * 2) {
        int e1 = e0 + 1;
        bool v1 = e1 < m;
        int s0 = __ldg(ls + e0), d0 = __ldg(ld + e0);
        int s1 = v1 ? __ldg(ls + e1) : s0;
        int d1 = v1 ? __ldg(ld + e1) : d0;
        uint4 a0 = __ldg(reinterpret_cast<const uint4*>(Up + (size_t)s0 * 128) + lane16);
        uint4 b0 = __ldg(reinterpret_cast<const uint4*>(Bp + (size_t)d0 * 128) + lane16);
        uint4 a1 = __ldg(reinterpret_cast<const uint4*>(Up + (size_t)s1 * 128) + lane16);
        uint4 b1 = __ldg(reinterpret_cast<const uint4*>(Bp + (size_t)d1 * 128) + lane16);
        float fa[8], fb[8];
        float dot0 = 0.f, dot1 = 0.f;
        {
            float2 p;
            p = __half22float2(*reinterpret_cast<__half2*>(&a0.x)); fa[0] = p.x; fa[1] = p.y;
            p = __half22float2(*reinterpret_cast<__half2*>(&a0.y)); fa[2] = p.x; fa[3] = p.y;
            p = __half22float2(*reinterpret_cast<__half2*>(&a0.z)); fa[4] = p.x; fa[5] = p.y;
            p = __half22float2(*reinterpret_cast<__half2*>(&a0.w)); fa[6] = p.x; fa[7] = p.y;
            p = __half22float2(*reinterpret_cast<__half2*>(&b0.x)); fb[0] = p.x; fb[1] = p.y;
            p = __half22float2(*reinterpret_cast<__half2*>(&b0.y)); fb[2] = p.x; fb[3] = p.y;
            p = __half22float2(*reinterpret_cast<__half2*>(&b0.z)); fb[4] = p.x; fb[5] = p.y;
            p = __half22float2(*reinterpret_cast<__half2*>(&b0.w)); fb[6] = p.x; fb[7] = p.y;
            #pragma unroll
            for (int i = 0; i < 8; i++) dot0 += fmaxf(fa[i] + fb[i], 0.f) * wv[i];
        }
        {
            float2 p;
            p = __half22float2(*reinterpret_cast<__half2*>(&a1.x)); fa[0] = p.x; fa[1] = p.y;
            p = __half22float2(*reinterpret_cast<__half2*>(&a1.y)); fa[2] = p.x; fa[3] = p.y;
            p = __half22float2(*reinterpret_cast<__half2*>(&a1.z)); fa[4] = p.x; fa[5] = p.y;
            p = __half22float2(*reinterpret_cast<__half2*>(&a1.w)); fa[6] = p.x; fa[7] = p.y;
            p = __half22float2(*reinterpret_cast<__half2*>(&b1.x)); fb[0] = p.x; fb[1] = p.y;
            p = __half22float2(*reinterpret_cast<__half2*>(&b1.y)); fb[2] = p.x; fb[3] = p.y;
            p = __half22float2(*reinterpret_cast<__half2*>(&b1.z)); fb[4] = p.x; fb[5] = p.y;
            p = __half22float2(*reinterpret_cast<__half2*>(&b1.w)); fb[6] = p.x; fb[7] = p.y;
            #pragma unroll
            for (int i = 0; i < 8; i++) dot1 += fmaxf(fa[i] + fb[i], 0.f) * wv[i];
        }
        #pragma unroll
        for (int off = 8; off > 0; off >>= 1) {
            dot0 += __shfl_xor_sync(FULL, dot0, off, 16);
            dot1 += __shfl_xor_sync(FULL, dot1, off, 16);
        }
        if (lane16 == 0) {
            out[e0] = dot0 + bb;
            if (v1) out[e1] = dot1 + bb;
        }
    }
}

// ---------------- host launcher ----------------
extern "C" void kernel_launch(void* const* d_in, const int* in_sizes, int n_in,
                              void* d_out, int out_size) {
    const float* user_x    = (const float*)d_in[0];
    const float* book_x    = (const float*)d_in[1];
    const int*   edge_src  = (const int*)d_in[2];
    const int*   edge_dst  = (const int*)d_in[3];
    const int*   label_src = (const int*)d_in[4];
    const int*   label_dst = (const int*)d_in[5];
    const float* user_lin_w = (const float*)d_in[6];
    const float* user_lin_b = (const float*)d_in[7];
    const float* book_lin_w = (const float*)d_in[8];
    const float* book_lin_b = (const float*)d_in[9];
    const float* w1_ub_l = (const float*)d_in[10];
    const float* b1_ub   = (const float*)d_in[11];
    const float* w1_ub_r = (const float*)d_in[12];
    const float* w1_bu_l = (const float*)d_in[13];
    const float* b1_bu   = (const float*)d_in[14];
    const float* w1_bu_r = (const float*)d_in[15];
    const float* w2_ub_l = (const float*)d_in[16];
    const float* b2_ub   = (const float*)d_in[17];
    const float* w2_ub_r = (const float*)d_in[18];
    const float* w2_bu_l = (const float*)d_in[19];
    const float* b2_bu   = (const float*)d_in[20];
    const float* w2_bu_r = (const float*)d_in[21];
    const float* dec_w1  = (const float*)d_in[22];
    const float* dec_b1  = (const float*)d_in[23];
    const float* dec_w2  = (const float*)d_in[24];
    const float* dec_b2  = (const float*)d_in[25];

    int nu = in_sizes[0] / 3;
    int nb = in_sizes[1] / 384;
    int E  = in_sizes[2];
    int EL = in_sizes[4];
    float* out = (float*)d_out;

    float *u0, *b0, *u1, *b1, *u2, *b2, *mu, *mb;
    __half *u0h, *b0h, *u1h, *b1h, *uph, *bph;
    int *degu, *degb, *offu, *offb, *posu, *posb, *nbu, *nub, *cnts, *bar;
    cudaGetSymbolAddress((void**)&u0, g_u0);
    cudaGetSymbolAddress((void**)&b0, g_b0);
    cudaGetSymbolAddress((void**)&u1, g_u1);
    cudaGetSymbolAddress((void**)&b1, g_b1);
    cudaGetSymbolAddress((void**)&u2, g_u2);
    cudaGetSymbolAddress((void**)&b2, g_b2);
    cudaGetSymbolAddress((void**)&mu, g_mu);
    cudaGetSymbolAddress((void**)&mb, g_mb);
    cudaGetSymbolAddress((void**)&u0h, g_u0h);
    cudaGetSymbolAddress((void**)&b0h, g_b0h);
    cudaGetSymbolAddress((void**)&u1h, g_u1h);
    cudaGetSymbolAddress((void**)&b1h, g_b1h);
    cudaGetSymbolAddress((void**)&uph, g_uph);
    cudaGetSymbolAddress((void**)&bph, g_bph);
    cudaGetSymbolAddress((void**)&degu, g_deg_u);
    cudaGetSymbolAddress((void**)&degb, g_deg_b);
    cudaGetSymbolAddress((void**)&offu, g_off_u);
    cudaGetSymbolAddress((void**)&offb, g_off_b);
    cudaGetSymbolAddress((void**)&posu, g_pos_u);
    cudaGetSymbolAddress((void**)&posb, g_pos_b);
    cudaGetSymbolAddress((void**)&nbu, g_nbr_b_of_u);
    cudaGetSymbolAddress((void**)&nub, g_nbr_u_of_b);
    cudaGetSymbolAddress((void**)&cnts, g_counters);
    cudaGetSymbolAddress((void**)&bar, g_bar);

    cudaFuncSetAttribute(proj2_kernel, cudaFuncAttributeMaxDynamicSharedMemorySize, PROJ_SMEM);
    cudaFuncSetAttribute(sage_transform2_kernel<true, true>,
                         cudaFuncAttributeMaxDynamicSharedMemorySize, SAGE_T_SMEM);
    cudaFuncSetAttribute(sage_transform2_kernel<false, false>,
                         cudaFuncAttributeMaxDynamicSharedMemorySize, SAGE_T_SMEM);
    cudaFuncSetAttribute(dec_pre2_kernel, cudaFuncAttributeMaxDynamicSharedMemorySize, DEC_P_SMEM);

    // 1: zero (deg arrays + counters + barrier slots)
    zero_all_kernel<<<(nu + 255) / 256, 256>>>(degu, nu, degb, nb, cnts, 2, bar, 2);
    // 2: fused CSR build
    csr_build_kernel<<<CSR_BLOCKS, 1024>>>(edge_src, edge_dst, degu, degb, posu, posb,
                                           offu, offb, nbu, nub, cnts, bar, nu, nb, E);
    // 3: fused projections
    {
        int ublocks = (nu * 16 + 255) / 256;
        proj2_kernel<<<ublocks + 296, 256, PROJ_SMEM>>>(
            user_x, user_lin_w, user_lin_b, u0, u0h, nu,
            book_x, book_lin_w, book_lin_b, b0, b0h, nb, ublocks);
    }
    // 4: layer-1 gather (profiled)
    sage_gather2_kernel<<<1184, 256>>>(u0h, offb, degb, nub, mb, nb,
                                       b0h, offu, degu, nbu, mu, nu, 592);
    sage_transform2_kernel<true, true><<<888, 256, SAGE_T_SMEM>>>(
        mb, b0, w1_ub_l, b1_ub, w1_ub_r, b1, b1h, nb,
        mu, u0, w1_bu_l, b1_bu, w1_bu_r, u1, u1h, nu, 296);

    // layer 2
    sage_gather2_kernel<<<1184, 256>>>(u1h, offb, degb, nub, mb, nb,
                                       b1h, offu, degu, nbu, mu, nu, 592);
    sage_transform2_kernel<false, false><<<888, 256, SAGE_T_SMEM>>>(
        mb, b1, w2_ub_l, b2_ub, w2_ub_r, b2, nullptr, nb,
        mu, u1, w2_bu_l, b2_bu, w2_bu_r, u2, nullptr, nu, 296);

    // decoder
    dec_pre2_kernel<<<888, 256, DEC_P_SMEM>>>(u2, dec_w1, dec_b1, uph, nu,
                                              b2, dec_w1 + 64 * 128, bph, nb, 592);
    dec_edge_kernel<<<1024, 256>>>(uph, bph, label_src, label_dst, dec_w2, dec_b2, out, EL);
}

// round 14
// speedup vs baseline: 1.0173x; 1.0173x over previous
#include <cuda_runtime.h>
#include <cuda_fp16.h>
#include <cstdint>
#include <cstddef>

#define NU_MAX 100000
#define NB_MAX 50000
#define E_MAX  2000000
#define C 64
#define H 128

// ---------------- device scratch (static, allocation-free) -----------
__device__ float g_u0[NU_MAX * C];
__device__ float g_b0[NB_MAX * C];
__device__ float g_u1[NU_MAX * C];
__device__ float g_b1[NB_MAX * C];
__device__ float g_u2[NU_MAX * C];
__device__ float g_b2[NB_MAX * C];
__device__ float g_mu[NU_MAX * C];
__device__ float g_mb[NB_MAX * C];
__device__ __half g_u0h[NU_MAX * C];
__device__ __half g_b0h[NB_MAX * C];
__device__ __half g_u1h[NU_MAX * C];
__device__ __half g_b1h[NB_MAX * C];
__device__ __half g_uph[NU_MAX * H];
__device__ __half g_bph[NB_MAX * H];
// CSR structures
__device__ int g_deg_u[NU_MAX];
__device__ int g_deg_b[NB_MAX];
__device__ int g_off_u[NU_MAX];
__device__ int g_off_b[NB_MAX];
__device__ int g_pos_u[E_MAX];
__device__ int g_pos_b[E_MAX];
__device__ int g_nbr_b_of_u[E_MAX];
__device__ int g_nbr_u_of_b[E_MAX];
__device__ int g_counters[2];

static __device__ __forceinline__ uint2 pack_half4(float a, float b, float c, float d) {
    __half2 h01 = __floats2half2_rn(a, b);
    __half2 h23 = __floats2half2_rn(c, d);
    uint2 r;
    r.x = *reinterpret_cast<unsigned*>(&h01);
    r.y = *reinterpret_cast<unsigned*>(&h23);
    return r;
}

// ---------------- utility ----------------
__global__ void zero_all_kernel(int* __restrict__ a, int na,
                                int* __restrict__ b, int nb_,
                                int* __restrict__ c, int nc) {
    int i = blockIdx.x * blockDim.x + threadIdx.x;
    if (i < na) a[i] = 0;
    if (i < nb_) b[i] = 0;
    if (i < nc) c[i] = 0;
}

// degree count + per-edge slot positions (atomic return value), 4 edges/thread
__global__ void deg_pos_kernel(const int* __restrict__ src, const int* __restrict__ dst,
                               int* __restrict__ degu, int* __restrict__ degb,
                               int* __restrict__ posu, int* __restrict__ posb, int E) {
    int t = blockIdx.x * blockDim.x + threadIdx.x;
    int i0 = t * 4;
    if (i0 + 3 < E) {
        int4 s4 = __ldg(reinterpret_cast<const int4*>(src) + t);
        int4 d4 = __ldg(reinterpret_cast<const int4*>(dst) + t);
        int4 pu, pb;
        pu.x = atomicAdd(degu + s4.x, 1);
        pu.y = atomicAdd(degu + s4.y, 1);
        pu.z = atomicAdd(degu + s4.z, 1);
        pu.w = atomicAdd(degu + s4.w, 1);
        pb.x = atomicAdd(degb + d4.x, 1);
        pb.y = atomicAdd(degb + d4.y, 1);
        pb.z = atomicAdd(degb + d4.z, 1);
        pb.w = atomicAdd(degb + d4.w, 1);
        reinterpret_cast<int4*>(posu)[t] = pu;
        reinterpret_cast<int4*>(posb)[t] = pb;
    } else {
        for (int k = 0; k < 4; k++) {
            int i = i0 + k;
            if (i < E) {
                posu[i] = atomicAdd(degu + __ldg(src + i), 1);
                posb[i] = atomicAdd(degb + __ldg(dst + i), 1);
            }
        }
    }
}

// fused parallel segment allocation for both sides (offsets only).
__global__ void alloc_offsets2_kernel(const int* __restrict__ degu, int* __restrict__ offu,
                                      const int* __restrict__ degb, int* __restrict__ offb,
                                      int* __restrict__ counters, int nu, int nb, int gu) {
    bool isU = (int)blockIdx.x < gu;
    const int* deg = isU ? degu : degb;
    int* off = isU ? offu : offb;
    int* counter = counters + (isU ? 0 : 1);
    int n = isU ? nu : nb;
    int bid = isU ? blockIdx.x : blockIdx.x - gu;

    __shared__ int s_warp[32];
    __shared__ int s_base;
    int tid = threadIdx.x, lane = tid & 31, wid = tid >> 5;
    int i = bid * 1024 + tid;
    int v = (i < n) ? deg[i] : 0;
    int x = v;
    #pragma unroll
    for (int o = 1; o < 32; o <<= 1) {
        int t = __shfl_up_sync(0xFFFFFFFFu, x, o);
        if (lane >= o) x += t;
    }
    if (lane == 31) s_warp[wid] = x;
    __syncthreads();
    if (wid == 0) {
        int w = s_warp[lane];
        #pragma unroll
        for (int o = 1; o < 32; o <<= 1) {
            int t = __shfl_up_sync(0xFFFFFFFFu, w, o);
            if (lane >= o) w += t;
        }
        s_warp[lane] = w;
    }
    __syncthreads();
    if (tid == 0) s_base = atomicAdd(counter, s_warp[31]);
    __syncthreads();
    int warpoff = (wid == 0) ? 0 : s_warp[wid - 1];
    int exc = s_base + warpoff + x - v;
    if (i < n) off[i] = exc;
}

// atomic-free scatter: slot = off[node] + pos[edge]
__global__ void scatter_pos_kernel(const int* __restrict__ src, const int* __restrict__ dst,
                                   const int* __restrict__ offu, const int* __restrict__ offb,
                                   const int* __restrict__ posu, const int* __restrict__ posb,
                                   int* __restrict__ nbr_b_of_u, int* __restrict__ nbr_u_of_b,
                                   int E) {
    int t = blockIdx.x * blockDim.x + threadIdx.x;
    int i0 = t * 4;
    if (i0 + 3 < E) {
        int4 s4 = __ldg(reinterpret_cast<const int4*>(src) + t);
        int4 d4 = __ldg(reinterpret_cast<const int4*>(dst) + t);
        int4 pu = __ldg(reinterpret_cast<const int4*>(posu) + t);
        int4 pb = __ldg(reinterpret_cast<const int4*>(posb) + t);
        int ou0 = __ldg(offu + s4.x), ou1 = __ldg(offu + s4.y);
        int ou2 = __ldg(offu + s4.z), ou3 = __ldg(offu + s4.w);
        int ob0 = __ldg(offb + d4.x), ob1 = __ldg(offb + d4.y);
        int ob2 = __ldg(offb + d4.z), ob3 = __ldg(offb + d4.w);
        nbr_b_of_u[ou0 + pu.x] = d4.x;
        nbr_b_of_u[ou1 + pu.y] = d4.y;
        nbr_b_of_u[ou2 + pu.z] = d4.z;
        nbr_b_of_u[ou3 + pu.w] = d4.w;
        nbr_u_of_b[ob0 + pb.x] = s4.x;
        nbr_u_of_b[ob1 + pb.y] = s4.y;
        nbr_u_of_b[ob2 + pb.z] = s4.z;
        nbr_u_of_b[ob3 + pb.w] = s4.w;
    } else {
        for (int k = 0; k < 4; k++) {
            int i = i0 + k;
            if (i < E) {
                int s = __ldg(src + i), d = __ldg(dst + i);
                nbr_b_of_u[__ldg(offu + s) + posu[i]] = d;
                nbr_u_of_b[__ldg(offb + d) + posb[i]] = s;
            }
        }
    }
}

// ---------------- fused projections (user elementwise + book staged GEMM) --------
#define PROJ_SMEM ((96 * 64 + 64 * 104 + 64) * 4)
__global__ void __launch_bounds__(256)
proj2_kernel(const float* __restrict__ ux, const float* __restrict__ uw,
             const float* __restrict__ ub, float* __restrict__ uout,
             __half* __restrict__ uouth, int nu,
             const float* __restrict__ bx, const float* __restrict__ bw,
             const float* __restrict__ bb, float* __restrict__ bout,
             __half* __restrict__ bouth, int nb, int ublocks) {
    if ((int)blockIdx.x < ublocks) {
        unsigned i = blockIdx.x * 256 + threadIdx.x;
        if (i >= (unsigned)nu * 16u) return;
        unsigned node = i >> 4, j4 = (i & 15u) * 4;
        const float* xr = ux + (size_t)node * 3;
        float x0 = __ldg(xr), x1 = __ldg(xr + 1), x2 = __ldg(xr + 2);
        float4 bbv = __ldg(reinterpret_cast<const float4*>(ub + j4));
        float4 w0 = __ldg(reinterpret_cast<const float4*>(uw + j4));
        float4 w1 = __ldg(reinterpret_cast<const float4*>(uw + 64 + j4));
        float4 w2 = __ldg(reinterpret_cast<const float4*>(uw + 128 + j4));
        float4 r;
        r.x = bbv.x + x0 * w0.x + x1 * w1.x + x2 * w2.x;
        r.y = bbv.y + x0 * w0.y + x1 * w1.y + x2 * w2.y;
        r.z = bbv.z + x0 * w0.z + x1 * w1.z + x2 * w2.z;
        r.w = bbv.w + x0 * w0.w + x1 * w1.w + x2 * w2.w;
        *reinterpret_cast<float4*>(uout + (size_t)node * 64 + j4) = r;
        *reinterpret_cast<uint2*>(uouth + (size_t)node * 64 + j4) = pack_half4(r.x, r.y, r.z, r.w);
        return;
    }
    extern __shared__ __align__(16) float dyn[];
    float* s_w = dyn;                   // 96*64
    float* s_a = dyn + 96 * 64;         // 64*104
    float* s_bias = s_a + 64 * 104;     // 64
    int tid = threadIdx.x;
    if (tid < 64) s_bias[tid] = bb[tid];
    int bid = blockIdx.x - ublocks;
    int gsz = gridDim.x - ublocks;
    int ty = tid >> 4, tx = tid & 15;
    int row = tid >> 2, seg = tid & 3;

    for (int tile = bid * 64; tile < nb; tile += gsz * 64) {
        float4 c[4];
        #pragma unroll
        for (int i = 0; i < 4; i++)
            c[i] = make_float4(0.f, 0.f, 0.f, 0.f);
        for (int ch = 0; ch < 4; ch++) {
            __syncthreads();
            for (int i = tid; i < 96 * 64 / 4; i += 256)
                reinterpret_cast<float4*>(s_w)[i] =
                    __ldg(reinterpret_cast<const float4*>(bw + ch * 96 * 64) + i);
            {
                int node = tile + row;
                float* dstp = s_a + row * 104 + seg * 24;
                if (node < nb) {
                    const float4* srcp = reinterpret_cast<const float4*>(
                        bx + (size_t)node * 384 + ch * 96 + seg * 24);
                    #pragma unroll
                    for (int q = 0; q < 6; q++)
                        reinterpret_cast<float4*>(dstp)[q] = __ldg(srcp + q);
                } else {
                    #pragma unroll
                    for (int q = 0; q < 6; q++)
                        reinterpret_cast<float4*>(dstp)[q] = make_float4(0.f, 0.f, 0.f, 0.f);
                }
            }
            __syncthreads();
            const float* a0p = s_a + (ty * 4 + 0) * 104;
            const float* a1p = s_a + (ty * 4 + 1) * 104;
            const float* a2p = s_a + (ty * 4 + 2) * 104;
            const float* a3p = s_a + (ty * 4 + 3) * 104;
            #pragma unroll 4
            for (int k = 0; k < 96; k++) {
                float4 w = *reinterpret_cast<const float4*>(s_w + k * 64 + tx * 4);
                float a0 = a0p[k], a1 = a1p[k], a2 = a2p[k], a3 = a3p[k];
                c[0].x += a0 * w.x; c[0].y += a0 * w.y; c[0].z += a0 * w.z; c[0].w += a0 * w.w;
                c[1].x += a1 * w.x; c[1].y += a1 * w.y; c[1].z += a1 * w.z; c[1].w += a1 * w.w;
                c[2].x += a2 * w.x; c[2].y += a2 * w.y; c[2].z += a2 * w.z; c[2].w += a2 * w.w;
                c[3].x += a3 * w.x; c[3].y += a3 * w.y; c[3].z += a3 * w.z; c[3].w += a3 * w.w;
            }
        }
        float4 bv = *reinterpret_cast<const float4*>(s_bias + tx * 4);
        #pragma unroll
        for (int i = 0; i < 4; i++) {
            int nd = tile + ty * 4 + i;
            if (nd < nb) {
                float4 r;
                r.x = c[i].x + bv.x; r.y = c[i].y + bv.y;
                r.z = c[i].z + bv.z; r.w = c[i].w + bv.w;
                *reinterpret_cast<float4*>(bout + (size_t)nd * 64 + tx * 4) = r;
                *reinterpret_cast<uint2*>(bouth + (size_t)nd * 64 + tx * 4) =
                    pack_half4(r.x, r.y, r.z, r.w);
            }
        }
    }
}

// ---------------- gather helpers ----------------
static __device__ __forceinline__ void addrow8(float* a, uint4 v) {
    float2 p0 = __half22float2(*reinterpret_cast<const __half2*>(&v.x));
    float2 p1 = __half22float2(*reinterpret_cast<const __half2*>(&v.y));
    float2 p2 = __half22float2(*reinterpret_cast<const __half2*>(&v.z));
    float2 p3 = __half22float2(*reinterpret_cast<const __half2*>(&v.w));
    a[0] += p0.x; a[1] += p0.y; a[2] += p1.x; a[3] += p1.y;
    a[4] += p2.x; a[5] += p2.y; a[6] += p3.x; a[7] += p3.y;
}

// pair-sum two fp16 rows with HADD2, convert once, fp32-accumulate.
static __device__ __forceinline__ void addpair8(float* a, uint4 u, uint4 v) {
    __half2 h0 = __hadd2(*reinterpret_cast<const __half2*>(&u.x),
                         *reinterpret_cast<const __half2*>(&v.x));
    __half2 h1 = __hadd2(*reinterpret_cast<const __half2*>(&u.y),
                         *reinterpret_cast<const __half2*>(&v.y));
    __half2 h2 = __hadd2(*reinterpret_cast<const __half2*>(&u.z),
                         *reinterpret_cast<const __half2*>(&v.z));
    __half2 h3 = __hadd2(*reinterpret_cast<const __half2*>(&u.w),
                         *reinterpret_cast<const __half2*>(&v.w));
    float2 p0 = __half22float2(h0);
    float2 p1 = __half22float2(h1);
    float2 p2 = __half22float2(h2);
    float2 p3 = __half22float2(h3);
    a[0] += p0.x; a[1] += p0.y; a[2] += p1.x; a[3] += p1.y;
    a[4] += p2.x; a[5] += p2.y; a[6] += p3.x; a[7] += p3.y;
}

// ---------------- fused dual-side sage gather: quarter-warp per node, HADD2 pairs ----
__global__ void __launch_bounds__(256)
sage_gather2_kernel(const __half* __restrict__ xA, const int* __restrict__ offA,
                    const int* __restrict__ degA, const int* __restrict__ nbrA,
                    float* __restrict__ mA, int nA,
                    const __half* __restrict__ xB, const int* __restrict__ offB,
                    const int* __restrict__ degB, const int* __restrict__ nbrB,
                    float* __restrict__ mB, int nB,
                    int gsplit) {
    const unsigned FULL = 0xFFFFFFFFu;
    const __half* xsrc;
    const int *offs, *degs, *nbr;
    float* mout;
    int n, bid, gsz;
    if ((int)blockIdx.x < gsplit) {
        xsrc = xA; offs = offA; degs = degA; nbr = nbrA; mout = mA; n = nA;
        bid = blockIdx.x; gsz = gsplit;
    } else {
        xsrc = xB; offs = offB; degs = degB; nbr = nbrB; mout = mB; n = nB;
        bid = blockIdx.x - gsplit; gsz = gridDim.x - gsplit;
    }
    int lane = threadIdx.x & 31, wid = threadIdx.x >> 5;
    int lane8 = lane & 7, quad = lane >> 3;

    for (int base = bid * 32 + wid * 4; base < n; base += gsz * 32) {
        int node = base + quad;
        bool valid = node < n;
        int beg = 0, dg = 0;
        if (valid) { beg = __ldg(offs + node); dg = __ldg(degs + node); }
        int nbq = (dg + 7) >> 3;
        int m1 = max(nbq, __shfl_xor_sync(FULL, nbq, 8));
        int nbatch = max(m1, __shfl_xor_sync(FULL, m1, 16));

        float accA[8] = {0.f, 0.f, 0.f, 0.f, 0.f, 0.f, 0.f, 0.f};
        float accB[8] = {0.f, 0.f, 0.f, 0.f, 0.f, 0.f, 0.f, 0.f};

        int sidx = (lane8 < dg) ? __ldg(nbr + beg + lane8) : 0;
        for (int b = 0; b < nbatch; b++) {
            int rem = dg - b * 8;
            int sidx_next = 0;
            if (b + 1 < nbatch) {
                int rem2 = dg - (b + 1) * 8;
                sidx_next = (lane8 < rem2) ? __ldg(nbr + beg + (b + 1) * 8 + lane8) : 0;
            }
            uint4 r[8];
            #pragma unroll
            for (int j = 0; j < 8; j++) {
                int s = __shfl_sync(FULL, sidx, j, 8);
                r[j] = __ldg(reinterpret_cast<const uint4*>(xsrc + (size_t)s * 64) + lane8);
            }
            // pairs (j, j+1): full pair -> HADD2 path; partial -> single-row path.
            #pragma unroll
            for (int j = 0; j < 8; j += 2) {
                float* acc = (j & 2) ? accB : accA;
                if (j + 1 < rem)      addpair8(acc, r[j], r[j + 1]);
                else if (j < rem)     addrow8(acc, r[j]);
            }
            sidx = sidx_next;
        }
        if (valid) {
            float inv = 1.0f / fmaxf((float)dg, 1.0f);
            float4 m0, m1v;
            m0.x = (accA[0] + accB[0]) * inv;
            m0.y = (accA[1] + accB[1]) * inv;
            m0.z = (accA[2] + accB[2]) * inv;
            m0.w = (accA[3] + accB[3]) * inv;
            m1v.x = (accA[4] + accB[4]) * inv;
            m1v.y = (accA[5] + accB[5]) * inv;
            m1v.z = (accA[6] + accB[6]) * inv;
            m1v.w = (accA[7] + accB[7]) * inv;
            float4* dst = reinterpret_cast<float4*>(mout + (size_t)node * 64 + lane8 * 8);
            dst[0] = m0;
            dst[1] = m1v;
        }
    }
}

// ---------------- fused dual-side sage transform: staged 64-node GEMM ----------------
#define SAGE_T_SMEM ((128 * 64 + 64 * 132 + 64) * 4)
template <bool RELU, bool EMIT_H>
__global__ void __launch_bounds__(256)
sage_transform2_kernel(const float* __restrict__ MA, const float* __restrict__ XA,
                       const float* __restrict__ wlA, const float* __restrict__ biasA,
                       const float* __restrict__ wrA,
                       float* __restrict__ outA, __half* __restrict__ outhA, int nA,
                       const float* __restrict__ MB, const float* __restrict__ XB,
                       const float* __restrict__ wlB, const float* __restrict__ biasB,
                       const float* __restrict__ wrB,
                       float* __restrict__ outB, __half* __restrict__ outhB, int nB,
                       int gsplit) {
    extern __shared__ __align__(16) float dyn[];
    float* s_w = dyn;                      // 128*64
    float* s_a = dyn + 128 * 64;           // 64*132
    float* s_bias = s_a + 64 * 132;        // 64

    const float *M, *X, *wl, *bias, *wr;
    float* out;
    __half* outh;
    int n, bid, gsz;
    if ((int)blockIdx.x < gsplit) {
        M = MA; X = XA; wl = wlA; bias = biasA; wr = wrA; out = outA; outh = outhA; n = nA;
        bid = blockIdx.x; gsz = gsplit;
    } else {
        M = MB; X = XB; wl = wlB; bias = biasB; wr = wrB; out = outB; outh = outhB; n = nB;
        bid = blockIdx.x - gsplit; gsz = gridDim.x - gsplit;
    }
    int tid = threadIdx.x;
    for (int i = tid; i < 64 * 64; i += 256) { s_w[i] = wl[i]; s_w[4096 + i] = wr[i]; }
    if (tid < 64) s_bias[tid] = bias[tid];
    int ty = tid >> 4, tx = tid & 15;
    int row = tid >> 2, seg = tid & 3;

    for (int tile = bid * 64; tile < n; tile += gsz * 64) {
        __syncthreads();
        {
            int node = tile + row;
            float* dstp = s_a + row * 132 + seg * 32;
            if (node < n) {
                const float* srcp = (seg < 2) ? (M + (size_t)node * 64 + seg * 32)
                                              : (X + (size_t)node * 64 + (seg - 2) * 32);
                #pragma unroll
                for (int q = 0; q < 8; q++)
                    reinterpret_cast<float4*>(dstp)[q] =
                        __ldg(reinterpret_cast<const float4*>(srcp) + q);
            } else {
                #pragma unroll
                for (int q = 0; q < 8; q++)
                    reinterpret_cast<float4*>(dstp)[q] = make_float4(0.f, 0.f, 0.f, 0.f);
            }
        }
        __syncthreads();
        float4 c0 = *reinterpret_cast<const float4*>(s_bias + tx * 4);
        float4 c1 = c0, c2 = c0, c3 = c0;
        const float* a0p = s_a + (ty * 4 + 0) * 132;
        const float* a1p = s_a + (ty * 4 + 1) * 132;
        const float* a2p = s_a + (ty * 4 + 2) * 132;
        const float* a3p = s_a + (ty * 4 + 3) * 132;
        #pragma unroll 4
        for (int k = 0; k < 128; k++) {
            float4 w = *reinterpret_cast<const float4*>(s_w + k * 64 + tx * 4);
            float a0 = a0p[k], a1 = a1p[k], a2 = a2p[k], a3 = a3p[k];
            c0.x += a0 * w.x; c0.y += a0 * w.y; c0.z += a0 * w.z; c0.w += a0 * w.w;
            c1.x += a1 * w.x; c1.y += a1 * w.y; c1.z += a1 * w.z; c1.w += a1 * w.w;
            c2.x += a2 * w.x; c2.y += a2 * w.y; c2.z += a2 * w.z; c2.w += a2 * w.w;
            c3.x += a3 * w.x; c3.y += a3 * w.y; c3.z += a3 * w.z; c3.w += a3 * w.w;
        }
        if (RELU) {
            c0.x = fmaxf(c0.x, 0.f); c0.y = fmaxf(c0.y, 0.f); c0.z = fmaxf(c0.z, 0.f); c0.w = fmaxf(c0.w, 0.f);
            c1.x = fmaxf(c1.x, 0.f); c1.y = fmaxf(c1.y, 0.f); c1.z = fmaxf(c1.z, 0.f); c1.w = fmaxf(c1.w, 0.f);
            c2.x = fmaxf(c2.x, 0.f); c2.y = fmaxf(c2.y, 0.f); c2.z = fmaxf(c2.z, 0.f); c2.w = fmaxf(c2.w, 0.f);
            c3.x = fmaxf(c3.x, 0.f); c3.y = fmaxf(c3.y, 0.f); c3.z = fmaxf(c3.z, 0.f); c3.w = fmaxf(c3.w, 0.f);
        }
        float4 cc[4] = {c0, c1, c2, c3};
        #pragma unroll
        for (int i = 0; i < 4; i++) {
            int nd = tile + ty * 4 + i;
            if (nd < n) {
                *reinterpret_cast<float4*>(out + (size_t)nd * 64 + tx * 4) = cc[i];
                if (EMIT_H)
                    *reinterpret_cast<uint2*>(outh + (size_t)nd * 64 + tx * 4) =
                        pack_half4(cc[i].x, cc[i].y, cc[i].z, cc[i].w);
            }
        }
    }
}

// ---------------- fused dual-side decoder precompute: staged GEMM --------------------
#define DEC_P_SMEM ((64 * 128 + 64 * 68 + 128) * 4)
__global__ void __launch_bounds__(256)
dec_pre2_kernel(const float* __restrict__ xA, const float* __restrict__ wA,
                const float* __restrict__ biasA, __half* __restrict__ outA, int nA,
                const float* __restrict__ xB, const float* __restrict__ wB,
                __half* __restrict__ outB, int nB, int gsplit) {
    extern __shared__ __align__(16) float dyn[];
    float* s_w = dyn;                      // 64*128
    float* s_a = dyn + 64 * 128;           // 64*68
    float* s_bias = s_a + 64 * 68;         // 128

    const float *x, *w, *bias;
    __half* out;
    int n, bid, gsz;
    if ((int)blockIdx.x < gsplit) {
        x = xA; w = wA; bias = biasA; out = outA; n = nA;
        bid = blockIdx.x; gsz = gsplit;
    } else {
        x = xB; w = wB; bias = nullptr; out = outB; n = nB;
        bid = blockIdx.x - gsplit; gsz = gridDim.x - gsplit;
    }
    int tid = threadIdx.x;
    for (int i = tid; i < 64 * 128; i += 256) s_w[i] = w[i];
    if (tid < 128) s_bias[tid] = bias ? bias[tid] : 0.f;
    int ty = tid >> 5, tx = tid & 31;
    int row = tid >> 2, seg = tid & 3;

    for (int tile = bid * 64; tile < n; tile += gsz * 64) {
        __syncthreads();
        {
            int node = tile + row;
            float* dstp = s_a + row * 68 + seg * 16;
            if (node < n) {
                const float4* srcp = reinterpret_cast<const float4*>(x + (size_t)node * 64 + seg * 16);
                #pragma unroll
                for (int q = 0; q < 4; q++)
                    reinterpret_cast<float4*>(dstp)[q] = __ldg(srcp + q);
            } else {
                #pragma unroll
                for (int q = 0; q < 4; q++)
                    reinterpret_cast<float4*>(dstp)[q] = make_float4(0.f, 0.f, 0.f, 0.f);
            }
        }
        __syncthreads();
        float4 b4 = *reinterpret_cast<const float4*>(s_bias + tx * 4);
        float4 c[8];
        #pragma unroll
        for (int i = 0; i < 8; i++) c[i] = b4;
        #pragma unroll 2
        for (int k = 0; k < 64; k++) {
            float4 w4 = *reinterpret_cast<const float4*>(s_w + k * 128 + tx * 4);
            #pragma unroll
            for (int i = 0; i < 8; i++) {
                float a = s_a[(ty * 8 + i) * 68 + k];
                c[i].x += a * w4.x; c[i].y += a * w4.y; c[i].z += a * w4.z; c[i].w += a * w4.w;
            }
        }
        #pragma unroll
        for (int i = 0; i < 8; i++) {
            int nd = tile + ty * 8 + i;
            if (nd < n)
                *reinterpret_cast<uint2*>(out + (size_t)nd * 128 + tx * 4) =
                    pack_half4(c[i].x, c[i].y, c[i].z, c[i].w);
        }
    }
}

// ---------------- decoder edge kernel: half-warp per edge, uint4 fp16 loads ----------
__global__ void __launch_bounds__(256)
dec_edge_kernel(const __half* __restrict__ Up, const __half* __restrict__ Bp,
                const int* __restrict__ ls, const int* __restrict__ ld,
                const float* __restrict__ w2, const float* __restrict__ b2,
                float* __restrict__ out, int m) {
    __shared__ float s_w2[128];
    if (threadIdx.x < 128) s_w2[threadIdx.x] = w2[threadIdx.x];
    __syncthreads();
    const unsigned FULL = 0xFFFFFFFFu;
    int lane = threadIdx.x & 31, wid = threadIdx.x >> 5;
    int lane16 = lane & 15, half = lane >> 4;
    float bb = __ldg(b2);
    float wv[8];
    #pragma unroll
    for (int i = 0; i < 8; i++) wv[i] = s_w2[lane16 * 8 + i];

    int ghalf = (blockIdx.x * 8 + wid) * 2 + half;
    int stride = gridDim.x * 16;
    for (int e0 = ghalf * 2; e0 < m; e0 += stride * 2) {
        int e1 = e0 + 1;
        bool v1 = e1 < m;
        int s0 = __ldg(ls + e0), d0 = __ldg(ld + e0);
        int s1 = v1 ? __ldg(ls + e1) : s0;
        int d1 = v1 ? __ldg(ld + e1) : d0;
        uint4 a0 = __ldg(reinterpret_cast<const uint4*>(Up + (size_t)s0 * 128) + lane16);
        uint4 b0 = __ldg(reinterpret_cast<const uint4*>(Bp + (size_t)d0 * 128) + lane16);
        uint4 a1 = __ldg(reinterpret_cast<const uint4*>(Up + (size_t)s1 * 128) + lane16);
        uint4 b1 = __ldg(reinterpret_cast<const uint4*>(Bp + (size_t)d1 * 128) + lane16);
        float fa[8], fb[8];
        float dot0 = 0.f, dot1 = 0.f;
        {
            float2 p;
            p = __half22float2(*reinterpret_cast<__half2*>(&a0.x)); fa[0] = p.x; fa[1] = p.y;
            p = __half22float2(*reinterpret_cast<__half2*>(&a0.y)); fa[2] = p.x; fa[3] = p.y;
            p = __half22float2(*reinterpret_cast<__half2*>(&a0.z)); fa[4] = p.x; fa[5] = p.y;
            p = __half22float2(*reinterpret_cast<__half2*>(&a0.w)); fa[6] = p.x; fa[7] = p.y;
            p = __half22float2(*reinterpret_cast<__half2*>(&b0.x)); fb[0] = p.x; fb[1] = p.y;
            p = __half22float2(*reinterpret_cast<__half2*>(&b0.y)); fb[2] = p.x; fb[3] = p.y;
            p = __half22float2(*reinterpret_cast<__half2*>(&b0.z)); fb[4] = p.x; fb[5] = p.y;
            p = __half22float2(*reinterpret_cast<__half2*>(&b0.w)); fb[6] = p.x; fb[7] = p.y;
            #pragma unroll
            for (int i = 0; i < 8; i++) dot0 += fmaxf(fa[i] + fb[i], 0.f) * wv[i];
        }
        {
            float2 p;
            p = __half22float2(*reinterpret_cast<__half2*>(&a1.x)); fa[0] = p.x; fa[1] = p.y;
            p = __half22float2(*reinterpret_cast<__half2*>(&a1.y)); fa[2] = p.x; fa[3] = p.y;
            p = __half22float2(*reinterpret_cast<__half2*>(&a1.z)); fa[4] = p.x; fa[5] = p.y;
            p = __half22float2(*reinterpret_cast<__half2*>(&a1.w)); fa[6] = p.x; fa[7] = p.y;
            p = __half22float2(*reinterpret_cast<__half2*>(&b1.x)); fb[0] = p.x; fb[1] = p.y;
            p = __half22float2(*reinterpret_cast<__half2*>(&b1.y)); fb[2] = p.x; fb[3] = p.y;
            p = __half22float2(*reinterpret_cast<__half2*>(&b1.z)); fb[4] = p.x; fb[5] = p.y;
            p = __half22float2(*reinterpret_cast<__half2*>(&b1.w)); fb[6] = p.x; fb[7] = p.y;
            #pragma unroll
            for (int i = 0; i < 8; i++) dot1 += fmaxf(fa[i] + fb[i], 0.f) * wv[i];
        }
        #pragma unroll
        for (int off = 8; off > 0; off >>= 1) {
            dot0 += __shfl_xor_sync(FULL, dot0, off, 16);
            dot1 += __shfl_xor_sync(FULL, dot1, off, 16);
        }
        if (lane16 == 0) {
            out[e0] = dot0 + bb;
            if (v1) out[e1] = dot1 + bb;
        }
    }
}

// ---------------- host launcher ----------------
extern "C" void kernel_launch(void* const* d_in, const int* in_sizes, int n_in,
                              void* d_out, int out_size) {
    const float* user_x    = (const float*)d_in[0];
    const float* book_x    = (const float*)d_in[1];
    const int*   edge_src  = (const int*)d_in[2];
    const int*   edge_dst  = (const int*)d_in[3];
    const int*   label_src = (const int*)d_in[4];
    const int*   label_dst = (const int*)d_in[5];
    const float* user_lin_w = (const float*)d_in[6];
    const float* user_lin_b = (const float*)d_in[7];
    const float* book_lin_w = (const float*)d_in[8];
    const float* book_lin_b = (const float*)d_in[9];
    const float* w1_ub_l = (const float*)d_in[10];
    const float* b1_ub   = (const float*)d_in[11];
    const float* w1_ub_r = (const float*)d_in[12];
    const float* w1_bu_l = (const float*)d_in[13];
    const float* b1_bu   = (const float*)d_in[14];
    const float* w1_bu_r = (const float*)d_in[15];
    const float* w2_ub_l = (const float*)d_in[16];
    const float* b2_ub   = (const float*)d_in[17];
    const float* w2_ub_r = (const float*)d_in[18];
    const float* w2_bu_l = (const float*)d_in[19];
    const float* b2_bu   = (const float*)d_in[20];
    const float* w2_bu_r = (const float*)d_in[21];
    const float* dec_w1  = (const float*)d_in[22];
    const float* dec_b1  = (const float*)d_in[23];
    const float* dec_w2  = (const float*)d_in[24];
    const float* dec_b2  = (const float*)d_in[25];

    int nu = in_sizes[0] / 3;
    int nb = in_sizes[1] / 384;
    int E  = in_sizes[2];
    int EL = in_sizes[4];
    float* out = (float*)d_out;

    float *u0, *b0, *u1, *b1, *u2, *b2, *mu, *mb;
    __half *u0h, *b0h, *u1h, *b1h, *uph, *bph;
    int *degu, *degb, *offu, *offb, *posu, *posb, *nbu, *nub, *cnts;
    cudaGetSymbolAddress((void**)&u0, g_u0);
    cudaGetSymbolAddress((void**)&b0, g_b0);
    cudaGetSymbolAddress((void**)&u1, g_u1);
    cudaGetSymbolAddress((void**)&b1, g_b1);
    cudaGetSymbolAddress((void**)&u2, g_u2);
    cudaGetSymbolAddress((void**)&b2, g_b2);
    cudaGetSymbolAddress((void**)&mu, g_mu);
    cudaGetSymbolAddress((void**)&mb, g_mb);
    cudaGetSymbolAddress((void**)&u0h, g_u0h);
    cudaGetSymbolAddress((void**)&b0h, g_b0h);
    cudaGetSymbolAddress((void**)&u1h, g_u1h);
    cudaGetSymbolAddress((void**)&b1h, g_b1h);
    cudaGetSymbolAddress((void**)&uph, g_uph);
    cudaGetSymbolAddress((void**)&bph, g_bph);
    cudaGetSymbolAddress((void**)&degu, g_deg_u);
    cudaGetSymbolAddress((void**)&degb, g_deg_b);
    cudaGetSymbolAddress((void**)&offu, g_off_u);
    cudaGetSymbolAddress((void**)&offb, g_off_b);
    cudaGetSymbolAddress((void**)&posu, g_pos_u);
    cudaGetSymbolAddress((void**)&posb, g_pos_b);
    cudaGetSymbolAddress((void**)&nbu, g_nbr_b_of_u);
    cudaGetSymbolAddress((void**)&nub, g_nbr_u_of_b);
    cudaGetSymbolAddress((void**)&cnts, g_counters);

    cudaFuncSetAttribute(proj2_kernel, cudaFuncAttributeMaxDynamicSharedMemorySize, PROJ_SMEM);
    cudaFuncSetAttribute(sage_transform2_kernel<true, true>,
                         cudaFuncAttributeMaxDynamicSharedMemorySize, SAGE_T_SMEM);
    cudaFuncSetAttribute(sage_transform2_kernel<false, false>,
                         cudaFuncAttributeMaxDynamicSharedMemorySize, SAGE_T_SMEM);
    cudaFuncSetAttribute(dec_pre2_kernel, cudaFuncAttributeMaxDynamicSharedMemorySize, DEC_P_SMEM);

    // ---- CSR build (separate kernels — persistent version regressed) ----
    zero_all_kernel<<<(nu + 255) / 256, 256>>>(degu, nu, degb, nb, cnts, 2);
    deg_pos_kernel<<<(E / 4 + 255) / 256, 256>>>(edge_src, edge_dst, degu, degb, posu, posb, E);
    int gu = (nu + 1023) / 1024, gb = (nb + 1023) / 1024;
    alloc_offsets2_kernel<<<gu + gb, 1024>>>(degu, offu, degb, offb, cnts, nu, nb, gu);
    scatter_pos_kernel<<<(E / 4 + 255) / 256, 256>>>(edge_src, edge_dst, offu, offb,
                                                     posu, posb, nbu, nub, E);

    // ---- fused projections ----
    {
        int ublocks = (nu * 16 + 255) / 256;
        proj2_kernel<<<ublocks + 296, 256, PROJ_SMEM>>>(
            user_x, user_lin_w, user_lin_b, u0, u0h, nu,
            book_x, book_lin_w, book_lin_b, b0, b0h, nb, ublocks);
    }

    // ---- layer 1 ----
    sage_gather2_kernel<<<1184, 256>>>(u0h, offb, degb, nub, mb, nb,
                                       b0h, offu, degu, nbu, mu, nu, 592);
    sage_transform2_kernel<true, true><<<888, 256, SAGE_T_SMEM>>>(
        mb, b0, w1_ub_l, b1_ub, w1_ub_r, b1, b1h, nb,
        mu, u0, w1_bu_l, b1_bu, w1_bu_r, u1, u1h, nu, 296);

    // ---- layer 2 ----
    sage_gather2_kernel<<<1184, 256>>>(u1h, offb, degb, nub, mb, nb,
                                       b1h, offu, degu, nbu, mu, nu, 592);
    sage_transform2_kernel<false, false><<<888, 256, SAGE_T_SMEM>>>(
        mb, b1, w2_ub_l, b2_ub, w2_ub_r, b2, nullptr, nb,
        mu, u1, w2_bu_l, b2_bu, w2_bu_r, u2, nullptr, nu, 296);

    // ---- decoder ----
    dec_pre2_kernel<<<888, 256, DEC_P_SMEM>>>(u2, dec_w1, dec_b1, uph, nu,
                                              b2, dec_w1 + 64 * 128, bph, nb, 592);
    dec_edge_kernel<<<1024, 256>>>(uph, bph, label_src, label_dst, dec_w2, dec_b2, out, EL);
}

// round 15
// speedup vs baseline: 1.1321x; 1.1129x over previous
#include <cuda_runtime.h>
#include <cuda_fp16.h>
#include <cstdint>
#include <cstddef>

#define NU_MAX 100000
#define NB_MAX 50000
#define E_MAX  2000000
#define C 64
#define H 128

// ---------------- device scratch (static, allocation-free) -----------
__device__ float g_u0[NU_MAX * C];
__device__ float g_b0[NB_MAX * C];
__device__ float g_u1[NU_MAX * C];
__device__ float g_b1[NB_MAX * C];
__device__ float g_u2[NU_MAX * C];
__device__ float g_b2[NB_MAX * C];
__device__ float g_mu[NU_MAX * C];
__device__ float g_mb[NB_MAX * C];
__device__ __half g_u0h[NU_MAX * C];
__device__ __half g_b0h[NB_MAX * C];
__device__ __half g_u1h[NU_MAX * C];
__device__ __half g_b1h[NB_MAX * C];
__device__ __half g_uph[NU_MAX * H];
__device__ __half g_bph[NB_MAX * H];
// CSR structures
__device__ int g_deg_u[NU_MAX];
__device__ int g_deg_b[NB_MAX];
__device__ int g_off_u[NU_MAX];
__device__ int g_off_b[NB_MAX];
__device__ int g_pos_u[E_MAX];
__device__ int g_pos_b[E_MAX];
__device__ int g_nbr_b_of_u[E_MAX];
__device__ int g_nbr_u_of_b[E_MAX];
__device__ int g_counters[2];

static __device__ __forceinline__ uint2 pack_half4(float a, float b, float c, float d) {
    __half2 h01 = __floats2half2_rn(a, b);
    __half2 h23 = __floats2half2_rn(c, d);
    uint2 r;
    r.x = *reinterpret_cast<unsigned*>(&h01);
    r.y = *reinterpret_cast<unsigned*>(&h23);
    return r;
}

// ---------------- utility ----------------
__global__ void zero_all_kernel(int* __restrict__ a, int na,
                                int* __restrict__ b, int nb_,
                                int* __restrict__ c, int nc) {
    int i = blockIdx.x * blockDim.x + threadIdx.x;
    if (i < na) a[i] = 0;
    if (i < nb_) b[i] = 0;
    if (i < nc) c[i] = 0;
}

// degree count + per-edge slot positions (atomic return value), 4 edges/thread
__global__ void deg_pos_kernel(const int* __restrict__ src, const int* __restrict__ dst,
                               int* __restrict__ degu, int* __restrict__ degb,
                               int* __restrict__ posu, int* __restrict__ posb, int E) {
    int t = blockIdx.x * blockDim.x + threadIdx.x;
    int i0 = t * 4;
    if (i0 + 3 < E) {
        int4 s4 = __ldg(reinterpret_cast<const int4*>(src) + t);
        int4 d4 = __ldg(reinterpret_cast<const int4*>(dst) + t);
        int4 pu, pb;
        pu.x = atomicAdd(degu + s4.x, 1);
        pu.y = atomicAdd(degu + s4.y, 1);
        pu.z = atomicAdd(degu + s4.z, 1);
        pu.w = atomicAdd(degu + s4.w, 1);
        pb.x = atomicAdd(degb + d4.x, 1);
        pb.y = atomicAdd(degb + d4.y, 1);
        pb.z = atomicAdd(degb + d4.z, 1);
        pb.w = atomicAdd(degb + d4.w, 1);
        reinterpret_cast<int4*>(posu)[t] = pu;
        reinterpret_cast<int4*>(posb)[t] = pb;
    } else {
        for (int k = 0; k < 4; k++) {
            int i = i0 + k;
            if (i < E) {
                posu[i] = atomicAdd(degu + __ldg(src + i), 1);
                posb[i] = atomicAdd(degb + __ldg(dst + i), 1);
            }
        }
    }
}

// fused parallel segment allocation for both sides (offsets only).
__global__ void alloc_offsets2_kernel(const int* __restrict__ degu, int* __restrict__ offu,
                                      const int* __restrict__ degb, int* __restrict__ offb,
                                      int* __restrict__ counters, int nu, int nb, int gu) {
    bool isU = (int)blockIdx.x < gu;
    const int* deg = isU ? degu : degb;
    int* off = isU ? offu : offb;
    int* counter = counters + (isU ? 0 : 1);
    int n = isU ? nu : nb;
    int bid = isU ? blockIdx.x : blockIdx.x - gu;

    __shared__ int s_warp[32];
    __shared__ int s_base;
    int tid = threadIdx.x, lane = tid & 31, wid = tid >> 5;
    int i = bid * 1024 + tid;
    int v = (i < n) ? deg[i] : 0;
    int x = v;
    #pragma unroll
    for (int o = 1; o < 32; o <<= 1) {
        int t = __shfl_up_sync(0xFFFFFFFFu, x, o);
        if (lane >= o) x += t;
    }
    if (lane == 31) s_warp[wid] = x;
    __syncthreads();
    if (wid == 0) {
        int w = s_warp[lane];
        #pragma unroll
        for (int o = 1; o < 32; o <<= 1) {
            int t = __shfl_up_sync(0xFFFFFFFFu, w, o);
            if (lane >= o) w += t;
        }
        s_warp[lane] = w;
    }
    __syncthreads();
    if (tid == 0) s_base = atomicAdd(counter, s_warp[31]);
    __syncthreads();
    int warpoff = (wid == 0) ? 0 : s_warp[wid - 1];
    int exc = s_base + warpoff + x - v;
    if (i < n) off[i] = exc;
}

// atomic-free scatter: slot = off[node] + pos[edge]
__global__ void scatter_pos_kernel(const int* __restrict__ src, const int* __restrict__ dst,
                                   const int* __restrict__ offu, const int* __restrict__ offb,
                                   const int* __restrict__ posu, const int* __restrict__ posb,
                                   int* __restrict__ nbr_b_of_u, int* __restrict__ nbr_u_of_b,
                                   int E) {
    int t = blockIdx.x * blockDim.x + threadIdx.x;
    int i0 = t * 4;
    if (i0 + 3 < E) {
        int4 s4 = __ldg(reinterpret_cast<const int4*>(src) + t);
        int4 d4 = __ldg(reinterpret_cast<const int4*>(dst) + t);
        int4 pu = __ldg(reinterpret_cast<const int4*>(posu) + t);
        int4 pb = __ldg(reinterpret_cast<const int4*>(posb) + t);
        int ou0 = __ldg(offu + s4.x), ou1 = __ldg(offu + s4.y);
        int ou2 = __ldg(offu + s4.z), ou3 = __ldg(offu + s4.w);
        int ob0 = __ldg(offb + d4.x), ob1 = __ldg(offb + d4.y);
        int ob2 = __ldg(offb + d4.z), ob3 = __ldg(offb + d4.w);
        nbr_b_of_u[ou0 + pu.x] = d4.x;
        nbr_b_of_u[ou1 + pu.y] = d4.y;
        nbr_b_of_u[ou2 + pu.z] = d4.z;
        nbr_b_of_u[ou3 + pu.w] = d4.w;
        nbr_u_of_b[ob0 + pb.x] = s4.x;
        nbr_u_of_b[ob1 + pb.y] = s4.y;
        nbr_u_of_b[ob2 + pb.z] = s4.z;
        nbr_u_of_b[ob3 + pb.w] = s4.w;
    } else {
        for (int k = 0; k < 4; k++) {
            int i = i0 + k;
            if (i < E) {
                int s = __ldg(src + i), d = __ldg(dst + i);
                nbr_b_of_u[__ldg(offu + s) + posu[i]] = d;
                nbr_u_of_b[__ldg(offb + d) + posb[i]] = s;
            }
        }
    }
}

// ---------------- input projections (emit fp32 + fp16) ----------------
__global__ void user_proj_kernel(const float* __restrict__ x, const float* __restrict__ w,
                                 const float* __restrict__ b, float* __restrict__ out,
                                 __half* __restrict__ outh, int n) {
    unsigned i = blockIdx.x * blockDim.x + threadIdx.x;
    if (i >= (unsigned)n * 16u) return;
    unsigned node = i >> 4, j4 = (i & 15u) * 4;
    const float* xr = x + (size_t)node * 3;
    float x0 = __ldg(xr), x1 = __ldg(xr + 1), x2 = __ldg(xr + 2);
    float4 bb = __ldg(reinterpret_cast<const float4*>(b + j4));
    float4 w0 = __ldg(reinterpret_cast<const float4*>(w + j4));
    float4 w1 = __ldg(reinterpret_cast<const float4*>(w + 64 + j4));
    float4 w2 = __ldg(reinterpret_cast<const float4*>(w + 128 + j4));
    float4 r;
    r.x = bb.x + x0 * w0.x + x1 * w1.x + x2 * w2.x;
    r.y = bb.y + x0 * w0.y + x1 * w1.y + x2 * w2.y;
    r.z = bb.z + x0 * w0.z + x1 * w1.z + x2 * w2.z;
    r.w = bb.w + x0 * w0.w + x1 * w1.w + x2 * w2.w;
    *reinterpret_cast<float4*>(out + (size_t)node * 64 + j4) = r;
    *reinterpret_cast<uint2*>(outh + (size_t)node * 64 + j4) = pack_half4(r.x, r.y, r.z, r.w);
}

// book: [n,384] @ [384,64] + b, full weights in dynamic smem, grid-stride.
__global__ void book_proj_kernel(const float* __restrict__ x, const float* __restrict__ w,
                                 const float* __restrict__ bias, float* __restrict__ out,
                                 __half* __restrict__ outh, int n) {
    extern __shared__ float dsm[];
    float* s_w = dsm;                 // 384*64
    float* s_rc = dsm + 384 * 64;     // 32 rows x 96
    int tid = threadIdx.x, lane = tid & 31, wid = tid >> 5;
    const float4* wsrc = reinterpret_cast<const float4*>(w);
    float4* wdst = reinterpret_cast<float4*>(s_w);
    for (int i = tid; i < 384 * 64 / 4; i += 256) wdst[i] = __ldg(wsrc + i);
    float2 bb = make_float2(__ldg(bias + lane * 2), __ldg(bias + lane * 2 + 1));
    __syncthreads();

    for (int g = blockIdx.x * 32; g < n; g += gridDim.x * 32) {
        int node0 = g + wid * 4;
        float2 acc[4];
        #pragma unroll
        for (int r = 0; r < 4; r++) acc[r] = bb;
        for (int ch = 0; ch < 4; ch++) {
            #pragma unroll
            for (int r = 0; r < 4; r++) {
                int nd = node0 + r;
                if (nd < n) {
                    const float* xr = x + (size_t)nd * 384 + ch * 96;
                    float* dst = s_rc + (wid * 4 + r) * 96;
                    dst[lane] = __ldg(xr + lane);
                    dst[lane + 32] = __ldg(xr + lane + 32);
                    dst[lane + 64] = __ldg(xr + lane + 64);
                }
            }
            __syncwarp();
            const float* wch = s_w + ch * 96 * 64;
            #pragma unroll 8
            for (int k = 0; k < 96; k++) {
                float2 wv = *reinterpret_cast<const float2*>(wch + k * 64 + lane * 2);
                #pragma unroll
                for (int r = 0; r < 4; r++) {
                    float xv = s_rc[(wid * 4 + r) * 96 + k];
                    acc[r].x += xv * wv.x;
                    acc[r].y += xv * wv.y;
                }
            }
            __syncwarp();
        }
        #pragma unroll
        for (int r = 0; r < 4; r++) {
            int nd = node0 + r;
            if (nd < n) {
                *reinterpret_cast<float2*>(out + (size_t)nd * 64 + lane * 2) = acc[r];
                __half2 h = __floats2half2_rn(acc[r].x, acc[r].y);
                *reinterpret_cast<unsigned*>(outh + (size_t)nd * 64 + lane * 2) =
                    *reinterpret_cast<unsigned*>(&h);
            }
        }
    }
}

// ---------------- gather helpers ----------------
static __device__ __forceinline__ void addrow8(float* a, uint4 v) {
    float2 p0 = __half22float2(*reinterpret_cast<const __half2*>(&v.x));
    float2 p1 = __half22float2(*reinterpret_cast<const __half2*>(&v.y));
    float2 p2 = __half22float2(*reinterpret_cast<const __half2*>(&v.z));
    float2 p3 = __half22float2(*reinterpret_cast<const __half2*>(&v.w));
    a[0] += p0.x; a[1] += p0.y; a[2] += p1.x; a[3] += p1.y;
    a[4] += p2.x; a[5] += p2.y; a[6] += p3.x; a[7] += p3.y;
}

// pair-sum two fp16 rows with HADD2, convert once, fp32-accumulate.
static __device__ __forceinline__ void addpair8(float* a, uint4 u, uint4 v) {
    __half2 h0 = __hadd2(*reinterpret_cast<const __half2*>(&u.x),
                         *reinterpret_cast<const __half2*>(&v.x));
    __half2 h1 = __hadd2(*reinterpret_cast<const __half2*>(&u.y),
                         *reinterpret_cast<const __half2*>(&v.y));
    __half2 h2 = __hadd2(*reinterpret_cast<const __half2*>(&u.z),
                         *reinterpret_cast<const __half2*>(&v.z));
    __half2 h3 = __hadd2(*reinterpret_cast<const __half2*>(&u.w),
                         *reinterpret_cast<const __half2*>(&v.w));
    float2 p0 = __half22float2(h0);
    float2 p1 = __half22float2(h1);
    float2 p2 = __half22float2(h2);
    float2 p3 = __half22float2(h3);
    a[0] += p0.x; a[1] += p0.y; a[2] += p1.x; a[3] += p1.y;
    a[4] += p2.x; a[5] += p2.y; a[6] += p3.x; a[7] += p3.y;
}

// ---------------- fused dual-side sage gather: quarter-warp per node, HADD2 pairs ----
__global__ void __launch_bounds__(256)
sage_gather2_kernel(const __half* __restrict__ xA, const int* __restrict__ offA,
                    const int* __restrict__ degA, const int* __restrict__ nbrA,
                    float* __restrict__ mA, int nA,
                    const __half* __restrict__ xB, const int* __restrict__ offB,
                    const int* __restrict__ degB, const int* __restrict__ nbrB,
                    float* __restrict__ mB, int nB,
                    int gsplit) {
    const unsigned FULL = 0xFFFFFFFFu;
    const __half* xsrc;
    const int *offs, *degs, *nbr;
    float* mout;
    int n, bid, gsz;
    if ((int)blockIdx.x < gsplit) {
        xsrc = xA; offs = offA; degs = degA; nbr = nbrA; mout = mA; n = nA;
        bid = blockIdx.x; gsz = gsplit;
    } else {
        xsrc = xB; offs = offB; degs = degB; nbr = nbrB; mout = mB; n = nB;
        bid = blockIdx.x - gsplit; gsz = gridDim.x - gsplit;
    }
    int lane = threadIdx.x & 31, wid = threadIdx.x >> 5;
    int lane8 = lane & 7, quad = lane >> 3;

    for (int base = bid * 32 + wid * 4; base < n; base += gsz * 32) {
        int node = base + quad;
        bool valid = node < n;
        int beg = 0, dg = 0;
        if (valid) { beg = __ldg(offs + node); dg = __ldg(degs + node); }
        int nbq = (dg + 7) >> 3;
        int m1 = max(nbq, __shfl_xor_sync(FULL, nbq, 8));
        int nbatch = max(m1, __shfl_xor_sync(FULL, m1, 16));

        float accA[8] = {0.f, 0.f, 0.f, 0.f, 0.f, 0.f, 0.f, 0.f};
        float accB[8] = {0.f, 0.f, 0.f, 0.f, 0.f, 0.f, 0.f, 0.f};

        int sidx = (lane8 < dg) ? __ldg(nbr + beg + lane8) : 0;
        for (int b = 0; b < nbatch; b++) {
            int rem = dg - b * 8;
            int sidx_next = 0;
            if (b + 1 < nbatch) {
                int rem2 = dg - (b + 1) * 8;
                sidx_next = (lane8 < rem2) ? __ldg(nbr + beg + (b + 1) * 8 + lane8) : 0;
            }
            uint4 r[8];
            #pragma unroll
            for (int j = 0; j < 8; j++) {
                int s = __shfl_sync(FULL, sidx, j, 8);
                r[j] = __ldg(reinterpret_cast<const uint4*>(xsrc + (size_t)s * 64) + lane8);
            }
            #pragma unroll
            for (int j = 0; j < 8; j += 2) {
                float* acc = (j & 2) ? accB : accA;
                if (j + 1 < rem)      addpair8(acc, r[j], r[j + 1]);
                else if (j < rem)     addrow8(acc, r[j]);
            }
            sidx = sidx_next;
        }
        if (valid) {
            float inv = 1.0f / fmaxf((float)dg, 1.0f);
            float4 m0, m1v;
            m0.x = (accA[0] + accB[0]) * inv;
            m0.y = (accA[1] + accB[1]) * inv;
            m0.z = (accA[2] + accB[2]) * inv;
            m0.w = (accA[3] + accB[3]) * inv;
            m1v.x = (accA[4] + accB[4]) * inv;
            m1v.y = (accA[5] + accB[5]) * inv;
            m1v.z = (accA[6] + accB[6]) * inv;
            m1v.w = (accA[7] + accB[7]) * inv;
            float4* dst = reinterpret_cast<float4*>(mout + (size_t)node * 64 + lane8 * 8);
            dst[0] = m0;
            dst[1] = m1v;
        }
    }
}

// ---------------- fused dual-side sage transform: staged 64-node GEMM ----------------
#define SAGE_T_SMEM ((128 * 64 + 64 * 132 + 64) * 4)
template <bool RELU, bool EMIT_H>
__global__ void __launch_bounds__(256)
sage_transform2_kernel(const float* __restrict__ MA, const float* __restrict__ XA,
                       const float* __restrict__ wlA, const float* __restrict__ biasA,
                       const float* __restrict__ wrA,
                       float* __restrict__ outA, __half* __restrict__ outhA, int nA,
                       const float* __restrict__ MB, const float* __restrict__ XB,
                       const float* __restrict__ wlB, const float* __restrict__ biasB,
                       const float* __restrict__ wrB,
                       float* __restrict__ outB, __half* __restrict__ outhB, int nB,
                       int gsplit) {
    extern __shared__ __align__(16) float dyn[];
    float* s_w = dyn;                      // 128*64
    float* s_a = dyn + 128 * 64;           // 64*132
    float* s_bias = s_a + 64 * 132;        // 64

    const float *M, *X, *wl, *bias, *wr;
    float* out;
    __half* outh;
    int n, bid, gsz;
    if ((int)blockIdx.x < gsplit) {
        M = MA; X = XA; wl = wlA; bias = biasA; wr = wrA; out = outA; outh = outhA; n = nA;
        bid = blockIdx.x; gsz = gsplit;
    } else {
        M = MB; X = XB; wl = wlB; bias = biasB; wr = wrB; out = outB; outh = outhB; n = nB;
        bid = blockIdx.x - gsplit; gsz = gridDim.x - gsplit;
    }
    int tid = threadIdx.x;
    for (int i = tid; i < 64 * 64; i += 256) { s_w[i] = wl[i]; s_w[4096 + i] = wr[i]; }
    if (tid < 64) s_bias[tid] = bias[tid];
    int ty = tid >> 4, tx = tid & 15;
    int row = tid >> 2, seg = tid & 3;

    for (int tile = bid * 64; tile < n; tile += gsz * 64) {
        __syncthreads();
        {
            int node = tile + row;
            float* dstp = s_a + row * 132 + seg * 32;
            if (node < n) {
                const float* srcp = (seg < 2) ? (M + (size_t)node * 64 + seg * 32)
                                              : (X + (size_t)node * 64 + (seg - 2) * 32);
                #pragma unroll
                for (int q = 0; q < 8; q++)
                    reinterpret_cast<float4*>(dstp)[q] =
                        __ldg(reinterpret_cast<const float4*>(srcp) + q);
            } else {
                #pragma unroll
                for (int q = 0; q < 8; q++)
                    reinterpret_cast<float4*>(dstp)[q] = make_float4(0.f, 0.f, 0.f, 0.f);
            }
        }
        __syncthreads();
        float4 c0 = *reinterpret_cast<const float4*>(s_bias + tx * 4);
        float4 c1 = c0, c2 = c0, c3 = c0;
        const float* a0p = s_a + (ty * 4 + 0) * 132;
        const float* a1p = s_a + (ty * 4 + 1) * 132;
        const float* a2p = s_a + (ty * 4 + 2) * 132;
        const float* a3p = s_a + (ty * 4 + 3) * 132;
        #pragma unroll 4
        for (int k = 0; k < 128; k++) {
            float4 w = *reinterpret_cast<const float4*>(s_w + k * 64 + tx * 4);
            float a0 = a0p[k], a1 = a1p[k], a2 = a2p[k], a3 = a3p[k];
            c0.x += a0 * w.x; c0.y += a0 * w.y; c0.z += a0 * w.z; c0.w += a0 * w.w;
            c1.x += a1 * w.x; c1.y += a1 * w.y; c1.z += a1 * w.z; c1.w += a1 * w.w;
            c2.x += a2 * w.x; c2.y += a2 * w.y; c2.z += a2 * w.z; c2.w += a2 * w.w;
            c3.x += a3 * w.x; c3.y += a3 * w.y; c3.z += a3 * w.z; c3.w += a3 * w.w;
        }
        if (RELU) {
            c0.x = fmaxf(c0.x, 0.f); c0.y = fmaxf(c0.y, 0.f); c0.z = fmaxf(c0.z, 0.f); c0.w = fmaxf(c0.w, 0.f);
            c1.x = fmaxf(c1.x, 0.f); c1.y = fmaxf(c1.y, 0.f); c1.z = fmaxf(c1.z, 0.f); c1.w = fmaxf(c1.w, 0.f);
            c2.x = fmaxf(c2.x, 0.f); c2.y = fmaxf(c2.y, 0.f); c2.z = fmaxf(c2.z, 0.f); c2.w = fmaxf(c2.w, 0.f);
            c3.x = fmaxf(c3.x, 0.f); c3.y = fmaxf(c3.y, 0.f); c3.z = fmaxf(c3.z, 0.f); c3.w = fmaxf(c3.w, 0.f);
        }
        float4 cc[4] = {c0, c1, c2, c3};
        #pragma unroll
        for (int i = 0; i < 4; i++) {
            int nd = tile + ty * 4 + i;
            if (nd < n) {
                *reinterpret_cast<float4*>(out + (size_t)nd * 64 + tx * 4) = cc[i];
                if (EMIT_H)
                    *reinterpret_cast<uint2*>(outh + (size_t)nd * 64 + tx * 4) =
                        pack_half4(cc[i].x, cc[i].y, cc[i].z, cc[i].w);
            }
        }
    }
}

// ---------------- fused dual-side decoder precompute: staged GEMM --------------------
#define DEC_P_SMEM ((64 * 128 + 64 * 68 + 128) * 4)
__global__ void __launch_bounds__(256)
dec_pre2_kernel(const float* __restrict__ xA, const float* __restrict__ wA,
                const float* __restrict__ biasA, __half* __restrict__ outA, int nA,
                const float* __restrict__ xB, const float* __restrict__ wB,
                __half* __restrict__ outB, int nB, int gsplit) {
    extern __shared__ __align__(16) float dyn[];
    float* s_w = dyn;                      // 64*128
    float* s_a = dyn + 64 * 128;           // 64*68
    float* s_bias = s_a + 64 * 68;         // 128

    const float *x, *w, *bias;
    __half* out;
    int n, bid, gsz;
    if ((int)blockIdx.x < gsplit) {
        x = xA; w = wA; bias = biasA; out = outA; n = nA;
        bid = blockIdx.x; gsz = gsplit;
    } else {
        x = xB; w = wB; bias = nullptr; out = outB; n = nB;
        bid = blockIdx.x - gsplit; gsz = gridDim.x - gsplit;
    }
    int tid = threadIdx.x;
    for (int i = tid; i < 64 * 128; i += 256) s_w[i] = w[i];
    if (tid < 128) s_bias[tid] = bias ? bias[tid] : 0.f;
    int ty = tid >> 5, tx = tid & 31;
    int row = tid >> 2, seg = tid & 3;

    for (int tile = bid * 64; tile < n; tile += gsz * 64) {
        __syncthreads();
        {
            int node = tile + row;
            float* dstp = s_a + row * 68 + seg * 16;
            if (node < n) {
                const float4* srcp = reinterpret_cast<const float4*>(x + (size_t)node * 64 + seg * 16);
                #pragma unroll
                for (int q = 0; q < 4; q++)
                    reinterpret_cast<float4*>(dstp)[q] = __ldg(srcp + q);
            } else {
                #pragma unroll
                for (int q = 0; q < 4; q++)
                    reinterpret_cast<float4*>(dstp)[q] = make_float4(0.f, 0.f, 0.f, 0.f);
            }
        }
        __syncthreads();
        float4 b4 = *reinterpret_cast<const float4*>(s_bias + tx * 4);
        float4 c[8];
        #pragma unroll
        for (int i = 0; i < 8; i++) c[i] = b4;
        #pragma unroll 2
        for (int k = 0; k < 64; k++) {
            float4 w4 = *reinterpret_cast<const float4*>(s_w + k * 128 + tx * 4);
            #pragma unroll
            for (int i = 0; i < 8; i++) {
                float a = s_a[(ty * 8 + i) * 68 + k];
                c[i].x += a * w4.x; c[i].y += a * w4.y; c[i].z += a * w4.z; c[i].w += a * w4.w;
            }
        }
        #pragma unroll
        for (int i = 0; i < 8; i++) {
            int nd = tile + ty * 8 + i;
            if (nd < n)
                *reinterpret_cast<uint2*>(out + (size_t)nd * 128 + tx * 4) =
                    pack_half4(c[i].x, c[i].y, c[i].z, c[i].w);
        }
    }
}

// ---------------- decoder edge kernel: half-warp per edge, uint4 fp16 loads ----------
__global__ void __launch_bounds__(256)
dec_edge_kernel(const __half* __restrict__ Up, const __half* __restrict__ Bp,
                const int* __restrict__ ls, const int* __restrict__ ld,
                const float* __restrict__ w2, const float* __restrict__ b2,
                float* __restrict__ out, int m) {
    __shared__ float s_w2[128];
    if (threadIdx.x < 128) s_w2[threadIdx.x] = w2[threadIdx.x];
    __syncthreads();
    const unsigned FULL = 0xFFFFFFFFu;
    int lane = threadIdx.x & 31, wid = threadIdx.x >> 5;
    int lane16 = lane & 15, half = lane >> 4;
    float bb = __ldg(b2);
    float wv[8];
    #pragma unroll
    for (int i = 0; i < 8; i++) wv[i] = s_w2[lane16 * 8 + i];

    int ghalf = (blockIdx.x * 8 + wid) * 2 + half;
    int stride = gridDim.x * 16;
    for (int e0 = ghalf * 2; e0 < m; e0 += stride * 2) {
        int e1 = e0 + 1;
        bool v1 = e1 < m;
        int s0 = __ldg(ls + e0), d0 = __ldg(ld + e0);
        int s1 = v1 ? __ldg(ls + e1) : s0;
        int d1 = v1 ? __ldg(ld + e1) : d0;
        uint4 a0 = __ldg(reinterpret_cast<const uint4*>(Up + (size_t)s0 * 128) + lane16);
        uint4 b0 = __ldg(reinterpret_cast<const uint4*>(Bp + (size_t)d0 * 128) + lane16);
        uint4 a1 = __ldg(reinterpret_cast<const uint4*>(Up + (size_t)s1 * 128) + lane16);
        uint4 b1 = __ldg(reinterpret_cast<const uint4*>(Bp + (size_t)d1 * 128) + lane16);
        float fa[8], fb[8];
        float dot0 = 0.f, dot1 = 0.f;
        {
            float2 p;
            p = __half22float2(*reinterpret_cast<__half2*>(&a0.x)); fa[0] = p.x; fa[1] = p.y;
            p = __half22float2(*reinterpret_cast<__half2*>(&a0.y)); fa[2] = p.x; fa[3] = p.y;
            p = __half22float2(*reinterpret_cast<__half2*>(&a0.z)); fa[4] = p.x; fa[5] = p.y;
            p = __half22float2(*reinterpret_cast<__half2*>(&a0.w)); fa[6] = p.x; fa[7] = p.y;
            p = __half22float2(*reinterpret_cast<__half2*>(&b0.x)); fb[0] = p.x; fb[1] = p.y;
            p = __half22float2(*reinterpret_cast<__half2*>(&b0.y)); fb[2] = p.x; fb[3] = p.y;
            p = __half22float2(*reinterpret_cast<__half2*>(&b0.z)); fb[4] = p.x; fb[5] = p.y;
            p = __half22float2(*reinterpret_cast<__half2*>(&b0.w)); fb[6] = p.x; fb[7] = p.y;
            #pragma unroll
            for (int i = 0; i < 8; i++) dot0 += fmaxf(fa[i] + fb[i], 0.f) * wv[i];
        }
        {
            float2 p;
            p = __half22float2(*reinterpret_cast<__half2*>(&a1.x)); fa[0] = p.x; fa[1] = p.y;
            p = __half22float2(*reinterpret_cast<__half2*>(&a1.y)); fa[2] = p.x; fa[3] = p.y;
            p = __half22float2(*reinterpret_cast<__half2*>(&a1.z)); fa[4] = p.x; fa[5] = p.y;
            p = __half22float2(*reinterpret_cast<__half2*>(&a1.w)); fa[6] = p.x; fa[7] = p.y;
            p = __half22float2(*reinterpret_cast<__half2*>(&b1.x)); fb[0] = p.x; fb[1] = p.y;
            p = __half22float2(*reinterpret_cast<__half2*>(&b1.y)); fb[2] = p.x; fb[3] = p.y;
            p = __half22float2(*reinterpret_cast<__half2*>(&b1.z)); fb[4] = p.x; fb[5] = p.y;
            p = __half22float2(*reinterpret_cast<__half2*>(&b1.w)); fb[6] = p.x; fb[7] = p.y;
            #pragma unroll
            for (int i = 0; i < 8; i++) dot1 += fmaxf(fa[i] + fb[i], 0.f) * wv[i];
        }
        #pragma unroll
        for (int off = 8; off > 0; off >>= 1) {
            dot0 += __shfl_xor_sync(FULL, dot0, off, 16);
            dot1 += __shfl_xor_sync(FULL, dot1, off, 16);
        }
        if (lane16 == 0) {
            out[e0] = dot0 + bb;
            if (v1) out[e1] = dot1 + bb;
        }
    }
}

// ---------------- host launcher ----------------
extern "C" void kernel_launch(void* const* d_in, const int* in_sizes, int n_in,
                              void* d_out, int out_size) {
    const float* user_x    = (const float*)d_in[0];
    const float* book_x    = (const float*)d_in[1];
    const int*   edge_src  = (const int*)d_in[2];
    const int*   edge_dst  = (const int*)d_in[3];
    const int*   label_src = (const int*)d_in[4];
    const int*   label_dst = (const int*)d_in[5];
    const float* user_lin_w = (const float*)d_in[6];
    const float* user_lin_b = (const float*)d_in[7];
    const float* book_lin_w = (const float*)d_in[8];
    const float* book_lin_b = (const float*)d_in[9];
    const float* w1_ub_l = (const float*)d_in[10];
    const float* b1_ub   = (const float*)d_in[11];
    const float* w1_ub_r = (const float*)d_in[12];
    const float* w1_bu_l = (const float*)d_in[13];
    const float* b1_bu   = (const float*)d_in[14];
    const float* w1_bu_r = (const float*)d_in[15];
    const float* w2_ub_l = (const float*)d_in[16];
    const float* b2_ub   = (const float*)d_in[17];
    const float* w2_ub_r = (const float*)d_in[18];
    const float* w2_bu_l = (const float*)d_in[19];
    const float* b2_bu   = (const float*)d_in[20];
    const float* w2_bu_r = (const float*)d_in[21];
    const float* dec_w1  = (const float*)d_in[22];
    const float* dec_b1  = (const float*)d_in[23];
    const float* dec_w2  = (const float*)d_in[24];
    const float* dec_b2  = (const float*)d_in[25];

    int nu = in_sizes[0] / 3;
    int nb = in_sizes[1] / 384;
    int E  = in_sizes[2];
    int EL = in_sizes[4];
    float* out = (float*)d_out;

    float *u0, *b0, *u1, *b1, *u2, *b2, *mu, *mb;
    __half *u0h, *b0h, *u1h, *b1h, *uph, *bph;
    int *degu, *degb, *offu, *offb, *posu, *posb, *nbu, *nub, *cnts;
    cudaGetSymbolAddress((void**)&u0, g_u0);
    cudaGetSymbolAddress((void**)&b0, g_b0);
    cudaGetSymbolAddress((void**)&u1, g_u1);
    cudaGetSymbolAddress((void**)&b1, g_b1);
    cudaGetSymbolAddress((void**)&u2, g_u2);
    cudaGetSymbolAddress((void**)&b2, g_b2);
    cudaGetSymbolAddress((void**)&mu, g_mu);
    cudaGetSymbolAddress((void**)&mb, g_mb);
    cudaGetSymbolAddress((void**)&u0h, g_u0h);
    cudaGetSymbolAddress((void**)&b0h, g_b0h);
    cudaGetSymbolAddress((void**)&u1h, g_u1h);
    cudaGetSymbolAddress((void**)&b1h, g_b1h);
    cudaGetSymbolAddress((void**)&uph, g_uph);
    cudaGetSymbolAddress((void**)&bph, g_bph);
    cudaGetSymbolAddress((void**)&degu, g_deg_u);
    cudaGetSymbolAddress((void**)&degb, g_deg_b);
    cudaGetSymbolAddress((void**)&offu, g_off_u);
    cudaGetSymbolAddress((void**)&offb, g_off_b);
    cudaGetSymbolAddress((void**)&posu, g_pos_u);
    cudaGetSymbolAddress((void**)&posb, g_pos_b);
    cudaGetSymbolAddress((void**)&nbu, g_nbr_b_of_u);
    cudaGetSymbolAddress((void**)&nub, g_nbr_u_of_b);
    cudaGetSymbolAddress((void**)&cnts, g_counters);

    static const int BOOK_SMEM = (384 * 64 + 32 * 96) * 4;
    cudaFuncSetAttribute(book_proj_kernel, cudaFuncAttributeMaxDynamicSharedMemorySize, BOOK_SMEM);
    cudaFuncSetAttribute(sage_transform2_kernel<true, true>,
                         cudaFuncAttributeMaxDynamicSharedMemorySize, SAGE_T_SMEM);
    cudaFuncSetAttribute(sage_transform2_kernel<false, false>,
                         cudaFuncAttributeMaxDynamicSharedMemorySize, SAGE_T_SMEM);
    cudaFuncSetAttribute(dec_pre2_kernel, cudaFuncAttributeMaxDynamicSharedMemorySize, DEC_P_SMEM);

    // ---- CSR build (position trick: no atomics in scatter) ----
    zero_all_kernel<<<(nu + 255) / 256, 256>>>(degu, nu, degb, nb, cnts, 2);
    deg_pos_kernel<<<(E / 4 + 255) / 256, 256>>>(edge_src, edge_dst, degu, degb, posu, posb, E);
    int gu = (nu + 1023) / 1024, gb = (nb + 1023) / 1024;
    alloc_offsets2_kernel<<<gu + gb, 1024>>>(degu, offu, degb, offb, cnts, nu, nb, gu);
    scatter_pos_kernel<<<(E / 4 + 255) / 256, 256>>>(edge_src, edge_dst, offu, offb,
                                                     posu, posb, nbu, nub, E);

    // ---- input projections ----
    {
        unsigned t = (unsigned)nu * 16u;
        user_proj_kernel<<<(t + 255) / 256, 256>>>(user_x, user_lin_w, user_lin_b, u0, u0h, nu);
    }
    book_proj_kernel<<<296, 256, BOOK_SMEM>>>(book_x, book_lin_w, book_lin_b, b0, b0h, nb);

    // ---- layer 1: fused dual gather + fused dual transform ----
    sage_gather2_kernel<<<1184, 256>>>(u0h, offb, degb, nub, mb, nb,
                                       b0h, offu, degu, nbu, mu, nu, 592);
    sage_transform2_kernel<true, true><<<888, 256, SAGE_T_SMEM>>>(
        mb, b0, w1_ub_l, b1_ub, w1_ub_r, b1, b1h, nb,
        mu, u0, w1_bu_l, b1_bu, w1_bu_r, u1, u1h, nu, 296);

    // ---- layer 2 ----
    sage_gather2_kernel<<<1184, 256>>>(u1h, offb, degb, nub, mb, nb,
                                       b1h, offu, degu, nbu, mu, nu, 592);
    sage_transform2_kernel<false, false><<<888, 256, SAGE_T_SMEM>>>(
        mb, b1, w2_ub_l, b2_ub, w2_ub_r, b2, nullptr, nb,
        mu, u1, w2_bu_l, b2_bu, w2_bu_r, u2, nullptr, nu, 296);

    // ---- decoder ----
    dec_pre2_kernel<<<888, 256, DEC_P_SMEM>>>(u2, dec_w1, dec_b1, uph, nu,
                                              b2, dec_w1 + 64 * 128, bph, nb, 592);
    dec_edge_kernel<<<1024, 256>>>(uph, bph, label_src, label_dst, dec_w2, dec_b2, out, EL);
}

// round 16
// speedup vs baseline: 1.1654x; 1.0294x over previous
#include <cuda_runtime.h>
#include <cuda_fp16.h>
#include <cstdint>
#include <cstddef>

#define NU_MAX 100000
#define NB_MAX 50000
#define E_MAX  2000000
#define C 64
#define H 128

// ---------------- device scratch (static, allocation-free) -----------
__device__ float g_u0[NU_MAX * C];
__device__ float g_b0[NB_MAX * C];
__device__ float g_u1[NU_MAX * C];
__device__ float g_b1[NB_MAX * C];
__device__ float g_u2[NU_MAX * C];
__device__ float g_b2[NB_MAX * C];
__device__ float g_mu[NU_MAX * C];
__device__ float g_mb[NB_MAX * C];
__device__ __half g_u0h[NU_MAX * C];
__device__ __half g_b0h[NB_MAX * C];
__device__ __half g_u1h[NU_MAX * C];
__device__ __half g_b1h[NB_MAX * C];
__device__ __half g_uph[NU_MAX * H];
__device__ __half g_bph[NB_MAX * H];
// CSR structures
__device__ int g_deg_u[NU_MAX];
__device__ int g_deg_b[NB_MAX];
__device__ int g_off_u[NU_MAX];
__device__ int g_off_b[NB_MAX];
__device__ int g_pos_u[E_MAX];
__device__ int g_pos_b[E_MAX];
__device__ int g_nbr_b_of_u[E_MAX];
__device__ int g_nbr_u_of_b[E_MAX];
__device__ int g_counters[2];

static __device__ __forceinline__ uint2 pack_half4(float a, float b, float c, float d) {
    __half2 h01 = __floats2half2_rn(a, b);
    __half2 h23 = __floats2half2_rn(c, d);
    uint2 r;
    r.x = *reinterpret_cast<unsigned*>(&h01);
    r.y = *reinterpret_cast<unsigned*>(&h23);
    return r;
}

// ---------------- utility ----------------
__global__ void zero_all_kernel(int* __restrict__ a, int na,
                                int* __restrict__ b, int nb_,
                                int* __restrict__ c, int nc) {
    int i = blockIdx.x * blockDim.x + threadIdx.x;
    if (i < na) a[i] = 0;
    if (i < nb_) b[i] = 0;
    if (i < nc) c[i] = 0;
}

// degree count + per-edge slot positions, 8 edges/thread for MLP
__global__ void deg_pos_kernel(const int* __restrict__ src, const int* __restrict__ dst,
                               int* __restrict__ degu, int* __restrict__ degb,
                               int* __restrict__ posu, int* __restrict__ posb, int E) {
    int t = blockIdx.x * blockDim.x + threadIdx.x;
    int i0 = t * 8;
    if (i0 + 7 < E) {
        int4 s4a = __ldg(reinterpret_cast<const int4*>(src) + t * 2);
        int4 s4b = __ldg(reinterpret_cast<const int4*>(src) + t * 2 + 1);
        int4 d4a = __ldg(reinterpret_cast<const int4*>(dst) + t * 2);
        int4 d4b = __ldg(reinterpret_cast<const int4*>(dst) + t * 2 + 1);
        int4 pua, pub, pba, pbb;
        pua.x = atomicAdd(degu + s4a.x, 1);
        pua.y = atomicAdd(degu + s4a.y, 1);
        pua.z = atomicAdd(degu + s4a.z, 1);
        pua.w = atomicAdd(degu + s4a.w, 1);
        pub.x = atomicAdd(degu + s4b.x, 1);
        pub.y = atomicAdd(degu + s4b.y, 1);
        pub.z = atomicAdd(degu + s4b.z, 1);
        pub.w = atomicAdd(degu + s4b.w, 1);
        pba.x = atomicAdd(degb + d4a.x, 1);
        pba.y = atomicAdd(degb + d4a.y, 1);
        pba.z = atomicAdd(degb + d4a.z, 1);
        pba.w = atomicAdd(degb + d4a.w, 1);
        pbb.x = atomicAdd(degb + d4b.x, 1);
        pbb.y = atomicAdd(degb + d4b.y, 1);
        pbb.z = atomicAdd(degb + d4b.z, 1);
        pbb.w = atomicAdd(degb + d4b.w, 1);
        reinterpret_cast<int4*>(posu)[t * 2]     = pua;
        reinterpret_cast<int4*>(posu)[t * 2 + 1] = pub;
        reinterpret_cast<int4*>(posb)[t * 2]     = pba;
        reinterpret_cast<int4*>(posb)[t * 2 + 1] = pbb;
    } else {
        for (int k = 0; k < 8; k++) {
            int i = i0 + k;
            if (i < E) {
                posu[i] = atomicAdd(degu + __ldg(src + i), 1);
                posb[i] = atomicAdd(degb + __ldg(dst + i), 1);
            }
        }
    }
}

// fused parallel segment allocation for both sides (offsets only).
__global__ void alloc_offsets2_kernel(const int* __restrict__ degu, int* __restrict__ offu,
                                      const int* __restrict__ degb, int* __restrict__ offb,
                                      int* __restrict__ counters, int nu, int nb, int gu) {
    bool isU = (int)blockIdx.x < gu;
    const int* deg = isU ? degu : degb;
    int* off = isU ? offu : offb;
    int* counter = counters + (isU ? 0 : 1);
    int n = isU ? nu : nb;
    int bid = isU ? blockIdx.x : blockIdx.x - gu;

    __shared__ int s_warp[32];
    __shared__ int s_base;
    int tid = threadIdx.x, lane = tid & 31, wid = tid >> 5;
    int i = bid * 1024 + tid;
    int v = (i < n) ? deg[i] : 0;
    int x = v;
    #pragma unroll
    for (int o = 1; o < 32; o <<= 1) {
        int t = __shfl_up_sync(0xFFFFFFFFu, x, o);
        if (lane >= o) x += t;
    }
    if (lane == 31) s_warp[wid] = x;
    __syncthreads();
    if (wid == 0) {
        int w = s_warp[lane];
        #pragma unroll
        for (int o = 1; o < 32; o <<= 1) {
            int t = __shfl_up_sync(0xFFFFFFFFu, w, o);
            if (lane >= o) w += t;
        }
        s_warp[lane] = w;
    }
    __syncthreads();
    if (tid == 0) s_base = atomicAdd(counter, s_warp[31]);
    __syncthreads();
    int warpoff = (wid == 0) ? 0 : s_warp[wid - 1];
    int exc = s_base + warpoff + x - v;
    if (i < n) off[i] = exc;
}

// atomic-free scatter: slot = off[node] + pos[edge], 8 edges/thread
__global__ void scatter_pos_kernel(const int* __restrict__ src, const int* __restrict__ dst,
                                   const int* __restrict__ offu, const int* __restrict__ offb,
                                   const int* __restrict__ posu, const int* __restrict__ posb,
                                   int* __restrict__ nbr_b_of_u, int* __restrict__ nbr_u_of_b,
                                   int E) {
    int t = blockIdx.x * blockDim.x + threadIdx.x;
    int i0 = t * 8;
    if (i0 + 7 < E) {
        int4 s4a = __ldg(reinterpret_cast<const int4*>(src) + t * 2);
        int4 s4b = __ldg(reinterpret_cast<const int4*>(src) + t * 2 + 1);
        int4 d4a = __ldg(reinterpret_cast<const int4*>(dst) + t * 2);
        int4 d4b = __ldg(reinterpret_cast<const int4*>(dst) + t * 2 + 1);
        int4 pua = __ldg(reinterpret_cast<const int4*>(posu) + t * 2);
        int4 pub = __ldg(reinterpret_cast<const int4*>(posu) + t * 2 + 1);
        int4 pba = __ldg(reinterpret_cast<const int4*>(posb) + t * 2);
        int4 pbb = __ldg(reinterpret_cast<const int4*>(posb) + t * 2 + 1);
        int ou0 = __ldg(offu + s4a.x), ou1 = __ldg(offu + s4a.y);
        int ou2 = __ldg(offu + s4a.z), ou3 = __ldg(offu + s4a.w);
        int ou4 = __ldg(offu + s4b.x), ou5 = __ldg(offu + s4b.y);
        int ou6 = __ldg(offu + s4b.z), ou7 = __ldg(offu + s4b.w);
        int ob0 = __ldg(offb + d4a.x), ob1 = __ldg(offb + d4a.y);
        int ob2 = __ldg(offb + d4a.z), ob3 = __ldg(offb + d4a.w);
        int ob4 = __ldg(offb + d4b.x), ob5 = __ldg(offb + d4b.y);
        int ob6 = __ldg(offb + d4b.z), ob7 = __ldg(offb + d4b.w);
        nbr_b_of_u[ou0 + pua.x] = d4a.x;
        nbr_b_of_u[ou1 + pua.y] = d4a.y;
        nbr_b_of_u[ou2 + pua.z] = d4a.z;
        nbr_b_of_u[ou3 + pua.w] = d4a.w;
        nbr_b_of_u[ou4 + pub.x] = d4b.x;
        nbr_b_of_u[ou5 + pub.y] = d4b.y;
        nbr_b_of_u[ou6 + pub.z] = d4b.z;
        nbr_b_of_u[ou7 + pub.w] = d4b.w;
        nbr_u_of_b[ob0 + pba.x] = s4a.x;
        nbr_u_of_b[ob1 + pba.y] = s4a.y;
        nbr_u_of_b[ob2 + pba.z] = s4a.z;
        nbr_u_of_b[ob3 + pba.w] = s4a.w;
        nbr_u_of_b[ob4 + pbb.x] = s4b.x;
        nbr_u_of_b[ob5 + pbb.y] = s4b.y;
        nbr_u_of_b[ob6 + pbb.z] = s4b.z;
        nbr_u_of_b[ob7 + pbb.w] = s4b.w;
    } else {
        for (int k = 0; k < 8; k++) {
            int i = i0 + k;
            if (i < E) {
                int s = __ldg(src + i), d = __ldg(dst + i);
                nbr_b_of_u[__ldg(offu + s) + posu[i]] = d;
                nbr_u_of_b[__ldg(offb + d) + posb[i]] = s;
            }
        }
    }
}

// ---------------- input projections (emit fp32 + fp16) ----------------
__global__ void user_proj_kernel(const float* __restrict__ x, const float* __restrict__ w,
                                 const float* __restrict__ b, float* __restrict__ out,
                                 __half* __restrict__ outh, int n) {
    unsigned i = blockIdx.x * blockDim.x + threadIdx.x;
    if (i >= (unsigned)n * 16u) return;
    unsigned node = i >> 4, j4 = (i & 15u) * 4;
    const float* xr = x + (size_t)node * 3;
    float x0 = __ldg(xr), x1 = __ldg(xr + 1), x2 = __ldg(xr + 2);
    float4 bb = __ldg(reinterpret_cast<const float4*>(b + j4));
    float4 w0 = __ldg(reinterpret_cast<const float4*>(w + j4));
    float4 w1 = __ldg(reinterpret_cast<const float4*>(w + 64 + j4));
    float4 w2 = __ldg(reinterpret_cast<const float4*>(w + 128 + j4));
    float4 r;
    r.x = bb.x + x0 * w0.x + x1 * w1.x + x2 * w2.x;
    r.y = bb.y + x0 * w0.y + x1 * w1.y + x2 * w2.y;
    r.z = bb.z + x0 * w0.z + x1 * w1.z + x2 * w2.z;
    r.w = bb.w + x0 * w0.w + x1 * w1.w + x2 * w2.w;
    *reinterpret_cast<float4*>(out + (size_t)node * 64 + j4) = r;
    *reinterpret_cast<uint2*>(outh + (size_t)node * 64 + j4) = pack_half4(r.x, r.y, r.z, r.w);
}

// book: [n,384] @ [384,64] + b, full weights in dynamic smem, grid-stride.
__global__ void book_proj_kernel(const float* __restrict__ x, const float* __restrict__ w,
                                 const float* __restrict__ bias, float* __restrict__ out,
                                 __half* __restrict__ outh, int n) {
    extern __shared__ float dsm[];
    float* s_w = dsm;                 // 384*64
    float* s_rc = dsm + 384 * 64;     // 32 rows x 96
    int tid = threadIdx.x, lane = tid & 31, wid = tid >> 5;
    const float4* wsrc = reinterpret_cast<const float4*>(w);
    float4* wdst = reinterpret_cast<float4*>(s_w);
    for (int i = tid; i < 384 * 64 / 4; i += 256) wdst[i] = __ldg(wsrc + i);
    float2 bb = make_float2(__ldg(bias + lane * 2), __ldg(bias + lane * 2 + 1));
    __syncthreads();

    for (int g = blockIdx.x * 32; g < n; g += gridDim.x * 32) {
        int node0 = g + wid * 4;
        float2 acc[4];
        #pragma unroll
        for (int r = 0; r < 4; r++) acc[r] = bb;
        for (int ch = 0; ch < 4; ch++) {
            #pragma unroll
            for (int r = 0; r < 4; r++) {
                int nd = node0 + r;
                if (nd < n) {
                    const float* xr = x + (size_t)nd * 384 + ch * 96;
                    float* dst = s_rc + (wid * 4 + r) * 96;
                    dst[lane] = __ldg(xr + lane);
                    dst[lane + 32] = __ldg(xr + lane + 32);
                    dst[lane + 64] = __ldg(xr + lane + 64);
                }
            }
            __syncwarp();
            const float* wch = s_w + ch * 96 * 64;
            #pragma unroll 8
            for (int k = 0; k < 96; k++) {
                float2 wv = *reinterpret_cast<const float2*>(wch + k * 64 + lane * 2);
                #pragma unroll
                for (int r = 0; r < 4; r++) {
                    float xv = s_rc[(wid * 4 + r) * 96 + k];
                    acc[r].x += xv * wv.x;
                    acc[r].y += xv * wv.y;
                }
            }
            __syncwarp();
        }
        #pragma unroll
        for (int r = 0; r < 4; r++) {
            int nd = node0 + r;
            if (nd < n) {
                *reinterpret_cast<float2*>(out + (size_t)nd * 64 + lane * 2) = acc[r];
                __half2 h = __floats2half2_rn(acc[r].x, acc[r].y);
                *reinterpret_cast<unsigned*>(outh + (size_t)nd * 64 + lane * 2) =
                    *reinterpret_cast<unsigned*>(&h);
            }
        }
    }
}

// ---------------- gather helpers ----------------
static __device__ __forceinline__ void addrow8(float* a, uint4 v) {
    float2 p0 = __half22float2(*reinterpret_cast<const __half2*>(&v.x));
    float2 p1 = __half22float2(*reinterpret_cast<const __half2*>(&v.y));
    float2 p2 = __half22float2(*reinterpret_cast<const __half2*>(&v.z));
    float2 p3 = __half22float2(*reinterpret_cast<const __half2*>(&v.w));
    a[0] += p0.x; a[1] += p0.y; a[2] += p1.x; a[3] += p1.y;
    a[4] += p2.x; a[5] += p2.y; a[6] += p3.x; a[7] += p3.y;
}

// pair-sum two fp16 rows with HADD2, convert once, fp32-accumulate.
static __device__ __forceinline__ void addpair8(float* a, uint4 u, uint4 v) {
    __half2 h0 = __hadd2(*reinterpret_cast<const __half2*>(&u.x),
                         *reinterpret_cast<const __half2*>(&v.x));
    __half2 h1 = __hadd2(*reinterpret_cast<const __half2*>(&u.y),
                         *reinterpret_cast<const __half2*>(&v.y));
    __half2 h2 = __hadd2(*reinterpret_cast<const __half2*>(&u.z),
                         *reinterpret_cast<const __half2*>(&v.z));
    __half2 h3 = __hadd2(*reinterpret_cast<const __half2*>(&u.w),
                         *reinterpret_cast<const __half2*>(&v.w));
    float2 p0 = __half22float2(h0);
    float2 p1 = __half22float2(h1);
    float2 p2 = __half22float2(h2);
    float2 p3 = __half22float2(h3);
    a[0] += p0.x; a[1] += p0.y; a[2] += p1.x; a[3] += p1.y;
    a[4] += p2.x; a[5] += p2.y; a[6] += p3.x; a[7] += p3.y;
}

// ---------------- fused dual-side sage gather: quarter-warp per node, HADD2 pairs ----
__global__ void __launch_bounds__(256)
sage_gather2_kernel(const __half* __restrict__ xA, const int* __restrict__ offA,
                    const int* __restrict__ degA, const int* __restrict__ nbrA,
                    float* __restrict__ mA, int nA,
                    const __half* __restrict__ xB, const int* __restrict__ offB,
                    const int* __restrict__ degB, const int* __restrict__ nbrB,
                    float* __restrict__ mB, int nB,
                    int gsplit) {
    const unsigned FULL = 0xFFFFFFFFu;
    const __half* xsrc;
    const int *offs, *degs, *nbr;
    float* mout;
    int n, bid, gsz;
    if ((int)blockIdx.x < gsplit) {
        xsrc = xA; offs = offA; degs = degA; nbr = nbrA; mout = mA; n = nA;
        bid = blockIdx.x; gsz = gsplit;
    } else {
        xsrc = xB; offs = offB; degs = degB; nbr = nbrB; mout = mB; n = nB;
        bid = blockIdx.x - gsplit; gsz = gridDim.x - gsplit;
    }
    int lane = threadIdx.x & 31, wid = threadIdx.x >> 5;
    int lane8 = lane & 7, quad = lane >> 3;

    for (int base = bid * 32 + wid * 4; base < n; base += gsz * 32) {
        int node = base + quad;
        bool valid = node < n;
        int beg = 0, dg = 0;
        if (valid) { beg = __ldg(offs + node); dg = __ldg(degs + node); }
        int nbq = (dg + 7) >> 3;
        int m1 = max(nbq, __shfl_xor_sync(FULL, nbq, 8));
        int nbatch = max(m1, __shfl_xor_sync(FULL, m1, 16));

        float accA[8] = {0.f, 0.f, 0.f, 0.f, 0.f, 0.f, 0.f, 0.f};
        float accB[8] = {0.f, 0.f, 0.f, 0.f, 0.f, 0.f, 0.f, 0.f};

        int sidx = (lane8 < dg) ? __ldg(nbr + beg + lane8) : 0;
        for (int b = 0; b < nbatch; b++) {
            int rem = dg - b * 8;
            int sidx_next = 0;
            if (b + 1 < nbatch) {
                int rem2 = dg - (b + 1) * 8;
                sidx_next = (lane8 < rem2) ? __ldg(nbr + beg + (b + 1) * 8 + lane8) : 0;
            }
            uint4 r[8];
            #pragma unroll
            for (int j = 0; j < 8; j++) {
                int s = __shfl_sync(FULL, sidx, j, 8);
                r[j] = __ldg(reinterpret_cast<const uint4*>(xsrc + (size_t)s * 64) + lane8);
            }
            #pragma unroll
            for (int j = 0; j < 8; j += 2) {
                float* acc = (j & 2) ? accB : accA;
                if (j + 1 < rem)      addpair8(acc, r[j], r[j + 1]);
                else if (j < rem)     addrow8(acc, r[j]);
            }
            sidx = sidx_next;
        }
        if (valid) {
            float inv = 1.0f / fmaxf((float)dg, 1.0f);
            float4 m0, m1v;
            m0.x = (accA[0] + accB[0]) * inv;
            m0.y = (accA[1] + accB[1]) * inv;
            m0.z = (accA[2] + accB[2]) * inv;
            m0.w = (accA[3] + accB[3]) * inv;
            m1v.x = (accA[4] + accB[4]) * inv;
            m1v.y = (accA[5] + accB[5]) * inv;
            m1v.z = (accA[6] + accB[6]) * inv;
            m1v.w = (accA[7] + accB[7]) * inv;
            float4* dst = reinterpret_cast<float4*>(mout + (size_t)node * 64 + lane8 * 8);
            dst[0] = m0;
            dst[1] = m1v;
        }
    }
}

// ---------------- fused dual-side sage transform: staged 64-node GEMM ----------------
#define SAGE_T_SMEM ((128 * 64 + 64 * 132 + 64) * 4)
template <bool RELU, bool EMIT_H>
__global__ void __launch_bounds__(256)
sage_transform2_kernel(const float* __restrict__ MA, const float* __restrict__ XA,
                       const float* __restrict__ wlA, const float* __restrict__ biasA,
                       const float* __restrict__ wrA,
                       float* __restrict__ outA, __half* __restrict__ outhA, int nA,
                       const float* __restrict__ MB, const float* __restrict__ XB,
                       const float* __restrict__ wlB, const float* __restrict__ biasB,
                       const float* __restrict__ wrB,
                       float* __restrict__ outB, __half* __restrict__ outhB, int nB,
                       int gsplit) {
    extern __shared__ __align__(16) float dyn[];
    float* s_w = dyn;                      // 128*64
    float* s_a = dyn + 128 * 64;           // 64*132
    float* s_bias = s_a + 64 * 132;        // 64

    const float *M, *X, *wl, *bias, *wr;
    float* out;
    __half* outh;
    int n, bid, gsz;
    if ((int)blockIdx.x < gsplit) {
        M = MA; X = XA; wl = wlA; bias = biasA; wr = wrA; out = outA; outh = outhA; n = nA;
        bid = blockIdx.x; gsz = gsplit;
    } else {
        M = MB; X = XB; wl = wlB; bias = biasB; wr = wrB; out = outB; outh = outhB; n = nB;
        bid = blockIdx.x - gsplit; gsz = gridDim.x - gsplit;
    }
    int tid = threadIdx.x;
    for (int i = tid; i < 64 * 64; i += 256) { s_w[i] = wl[i]; s_w[4096 + i] = wr[i]; }
    if (tid < 64) s_bias[tid] = bias[tid];
    int ty = tid >> 4, tx = tid & 15;
    int row = tid >> 2, seg = tid & 3;

    for (int tile = bid * 64; tile < n; tile += gsz * 64) {
        __syncthreads();
        {
            int node = tile + row;
            float* dstp = s_a + row * 132 + seg * 32;
            if (node < n) {
                const float* srcp = (seg < 2) ? (M + (size_t)node * 64 + seg * 32)
                                              : (X + (size_t)node * 64 + (seg - 2) * 32);
                #pragma unroll
                for (int q = 0; q < 8; q++)
                    reinterpret_cast<float4*>(dstp)[q] =
                        __ldg(reinterpret_cast<const float4*>(srcp) + q);
            } else {
                #pragma unroll
                for (int q = 0; q < 8; q++)
                    reinterpret_cast<float4*>(dstp)[q] = make_float4(0.f, 0.f, 0.f, 0.f);
            }
        }
        __syncthreads();
        float4 c0 = *reinterpret_cast<const float4*>(s_bias + tx * 4);
        float4 c1 = c0, c2 = c0, c3 = c0;
        const float* a0p = s_a + (ty * 4 + 0) * 132;
        const float* a1p = s_a + (ty * 4 + 1) * 132;
        const float* a2p = s_a + (ty * 4 + 2) * 132;
        const float* a3p = s_a + (ty * 4 + 3) * 132;
        #pragma unroll 4
        for (int k = 0; k < 128; k++) {
            float4 w = *reinterpret_cast<const float4*>(s_w + k * 64 + tx * 4);
            float a0 = a0p[k], a1 = a1p[k], a2 = a2p[k], a3 = a3p[k];
            c0.x += a0 * w.x; c0.y += a0 * w.y; c0.z += a0 * w.z; c0.w += a0 * w.w;
            c1.x += a1 * w.x; c1.y += a1 * w.y; c1.z += a1 * w.z; c1.w += a1 * w.w;
            c2.x += a2 * w.x; c2.y += a2 * w.y; c2.z += a2 * w.z; c2.w += a2 * w.w;
            c3.x += a3 * w.x; c3.y += a3 * w.y; c3.z += a3 * w.z; c3.w += a3 * w.w;
        }
        if (RELU) {
            c0.x = fmaxf(c0.x, 0.f); c0.y = fmaxf(c0.y, 0.f); c0.z = fmaxf(c0.z, 0.f); c0.w = fmaxf(c0.w, 0.f);
            c1.x = fmaxf(c1.x, 0.f); c1.y = fmaxf(c1.y, 0.f); c1.z = fmaxf(c1.z, 0.f); c1.w = fmaxf(c1.w, 0.f);
            c2.x = fmaxf(c2.x, 0.f); c2.y = fmaxf(c2.y, 0.f); c2.z = fmaxf(c2.z, 0.f); c2.w = fmaxf(c2.w, 0.f);
            c3.x = fmaxf(c3.x, 0.f); c3.y = fmaxf(c3.y, 0.f); c3.z = fmaxf(c3.z, 0.f); c3.w = fmaxf(c3.w, 0.f);
        }
        float4 cc[4] = {c0, c1, c2, c3};
        #pragma unroll
        for (int i = 0; i < 4; i++) {
            int nd = tile + ty * 4 + i;
            if (nd < n) {
                *reinterpret_cast<float4*>(out + (size_t)nd * 64 + tx * 4) = cc[i];
                if (EMIT_H)
                    *reinterpret_cast<uint2*>(outh + (size_t)nd * 64 + tx * 4) =
                        pack_half4(cc[i].x, cc[i].y, cc[i].z, cc[i].w);
            }
        }
    }
}

// ---------------- fused dual-side decoder precompute: staged GEMM --------------------
#define DEC_P_SMEM ((64 * 128 + 64 * 68 + 128) * 4)
__global__ void __launch_bounds__(256)
dec_pre2_kernel(const float* __restrict__ xA, const float* __restrict__ wA,
                const float* __restrict__ biasA, __half* __restrict__ outA, int nA,
                const float* __restrict__ xB, const float* __restrict__ wB,
                __half* __restrict__ outB, int nB, int gsplit) {
    extern __shared__ __align__(16) float dyn[];
    float* s_w = dyn;                      // 64*128
    float* s_a = dyn + 64 * 128;           // 64*68
    float* s_bias = s_a + 64 * 68;         // 128

    const float *x, *w, *bias;
    __half* out;
    int n, bid, gsz;
    if ((int)blockIdx.x < gsplit) {
        x = xA; w = wA; bias = biasA; out = outA; n = nA;
        bid = blockIdx.x; gsz = gsplit;
    } else {
        x = xB; w = wB; bias = nullptr; out = outB; n = nB;
        bid = blockIdx.x - gsplit; gsz = gridDim.x - gsplit;
    }
    int tid = threadIdx.x;
    for (int i = tid; i < 64 * 128; i += 256) s_w[i] = w[i];
    if (tid < 128) s_bias[tid] = bias ? bias[tid] : 0.f;
    int ty = tid >> 5, tx = tid & 31;
    int row = tid >> 2, seg = tid & 3;

    for (int tile = bid * 64; tile < n; tile += gsz * 64) {
        __syncthreads();
        {
            int node = tile + row;
            float* dstp = s_a + row * 68 + seg * 16;
            if (node < n) {
                const float4* srcp = reinterpret_cast<const float4*>(x + (size_t)node * 64 + seg * 16);
                #pragma unroll
                for (int q = 0; q < 4; q++)
                    reinterpret_cast<float4*>(dstp)[q] = __ldg(srcp + q);
            } else {
                #pragma unroll
                for (int q = 0; q < 4; q++)
                    reinterpret_cast<float4*>(dstp)[q] = make_float4(0.f, 0.f, 0.f, 0.f);
            }
        }
        __syncthreads();
        float4 b4 = *reinterpret_cast<const float4*>(s_bias + tx * 4);
        float4 c[8];
        #pragma unroll
        for (int i = 0; i < 8; i++) c[i] = b4;
        #pragma unroll 2
        for (int k = 0; k < 64; k++) {
            float4 w4 = *reinterpret_cast<const float4*>(s_w + k * 128 + tx * 4);
            #pragma unroll
            for (int i = 0; i < 8; i++) {
                float a = s_a[(ty * 8 + i) * 68 + k];
                c[i].x += a * w4.x; c[i].y += a * w4.y; c[i].z += a * w4.z; c[i].w += a * w4.w;
            }
        }
        #pragma unroll
        for (int i = 0; i < 8; i++) {
            int nd = tile + ty * 8 + i;
            if (nd < n)
                *reinterpret_cast<uint2*>(out + (size_t)nd * 128 + tx * 4) =
                    pack_half4(c[i].x, c[i].y, c[i].z, c[i].w);
        }
    }
}

// ---------------- decoder edge kernel: half-warp per edge, uint4 fp16 loads ----------
__global__ void __launch_bounds__(256)
dec_edge_kernel(const __half* __restrict__ Up, const __half* __restrict__ Bp,
                const int* __restrict__ ls, const int* __restrict__ ld,
                const float* __restrict__ w2, const float* __restrict__ b2,
                float* __restrict__ out, int m) {
    __shared__ float s_w2[128];
    if (threadIdx.x < 128) s_w2[threadIdx.x] = w2[threadIdx.x];
    __syncthreads();
    const unsigned FULL = 0xFFFFFFFFu;
    int lane = threadIdx.x & 31, wid = threadIdx.x >> 5;
    int lane16 = lane & 15, half = lane >> 4;
    float bb = __ldg(b2);
    float wv[8];
    #pragma unroll
    for (int i = 0; i < 8; i++) wv[i] = s_w2[lane16 * 8 + i];

    int ghalf = (blockIdx.x * 8 + wid) * 2 + half;
    int stride = gridDim.x * 16;
    for (int e0 = ghalf * 2; e0 < m; e0 += stride * 2) {
        int e1 = e0 + 1;
        bool v1 = e1 < m;
        int s0 = __ldg(ls + e0), d0 = __ldg(ld + e0);
        int s1 = v1 ? __ldg(ls + e1) : s0;
        int d1 = v1 ? __ldg(ld + e1) : d0;
        uint4 a0 = __ldg(reinterpret_cast<const uint4*>(Up + (size_t)s0 * 128) + lane16);
        uint4 b0 = __ldg(reinterpret_cast<const uint4*>(Bp + (size_t)d0 * 128) + lane16);
        uint4 a1 = __ldg(reinterpret_cast<const uint4*>(Up + (size_t)s1 * 128) + lane16);
        uint4 b1 = __ldg(reinterpret_cast<const uint4*>(Bp + (size_t)d1 * 128) + lane16);
        float fa[8], fb[8];
        float dot0 = 0.f, dot1 = 0.f;
        {
            float2 p;
            p = __half22float2(*reinterpret_cast<__half2*>(&a0.x)); fa[0] = p.x; fa[1] = p.y;
            p = __half22float2(*reinterpret_cast<__half2*>(&a0.y)); fa[2] = p.x; fa[3] = p.y;
            p = __half22float2(*reinterpret_cast<__half2*>(&a0.z)); fa[4] = p.x; fa[5] = p.y;
            p = __half22float2(*reinterpret_cast<__half2*>(&a0.w)); fa[6] = p.x; fa[7] = p.y;
            p = __half22float2(*reinterpret_cast<__half2*>(&b0.x)); fb[0] = p.x; fb[1] = p.y;
            p = __half22float2(*reinterpret_cast<__half2*>(&b0.y)); fb[2] = p.x; fb[3] = p.y;
            p = __half22float2(*reinterpret_cast<__half2*>(&b0.z)); fb[4] = p.x; fb[5] = p.y;
            p = __half22float2(*reinterpret_cast<__half2*>(&b0.w)); fb[6] = p.x; fb[7] = p.y;
            #pragma unroll
            for (int i = 0; i < 8; i++) dot0 += fmaxf(fa[i] + fb[i], 0.f) * wv[i];
        }
        {
            float2 p;
            p = __half22float2(*reinterpret_cast<__half2*>(&a1.x)); fa[0] = p.x; fa[1] = p.y;
            p = __half22float2(*reinterpret_cast<__half2*>(&a1.y)); fa[2] = p.x; fa[3] = p.y;
            p = __half22float2(*reinterpret_cast<__half2*>(&a1.z)); fa[4] = p.x; fa[5] = p.y;
            p = __half22float2(*reinterpret_cast<__half2*>(&a1.w)); fa[6] = p.x; fa[7] = p.y;
            p = __half22float2(*reinterpret_cast<__half2*>(&b1.x)); fb[0] = p.x; fb[1] = p.y;
            p = __half22float2(*reinterpret_cast<__half2*>(&b1.y)); fb[2] = p.x; fb[3] = p.y;
            p = __half22float2(*reinterpret_cast<__half2*>(&b1.z)); fb[4] = p.x; fb[5] = p.y;
            p = __half22float2(*reinterpret_cast<__half2*>(&b1.w)); fb[6] = p.x; fb[7] = p.y;
            #pragma unroll
            for (int i = 0; i < 8; i++) dot1 += fmaxf(fa[i] + fb[i], 0.f) * wv[i];
        }
        #pragma unroll
        for (int off = 8; off > 0; off >>= 1) {
            dot0 += __shfl_xor_sync(FULL, dot0, off, 16);
            dot1 += __shfl_xor_sync(FULL, dot1, off, 16);
        }
        if (lane16 == 0) {
            out[e0] = dot0 + bb;
            if (v1) out[e1] = dot1 + bb;
        }
    }
}

// ---------------- host launcher ----------------
extern "C" void kernel_launch(void* const* d_in, const int* in_sizes, int n_in,
                              void* d_out, int out_size) {
    const float* user_x    = (const float*)d_in[0];
    const float* book_x    = (const float*)d_in[1];
    const int*   edge_src  = (const int*)d_in[2];
    const int*   edge_dst  = (const int*)d_in[3];
    const int*   label_src = (const int*)d_in[4];
    const int*   label_dst = (const int*)d_in[5];
    const float* user_lin_w = (const float*)d_in[6];
    const float* user_lin_b = (const float*)d_in[7];
    const float* book_lin_w = (const float*)d_in[8];
    const float* book_lin_b = (const float*)d_in[9];
    const float* w1_ub_l = (const float*)d_in[10];
    const float* b1_ub   = (const float*)d_in[11];
    const float* w1_ub_r = (const float*)d_in[12];
    const float* w1_bu_l = (const float*)d_in[13];
    const float* b1_bu   = (const float*)d_in[14];
    const float* w1_bu_r = (const float*)d_in[15];
    const float* w2_ub_l = (const float*)d_in[16];
    const float* b2_ub   = (const float*)d_in[17];
    const float* w2_ub_r = (const float*)d_in[18];
    const float* w2_bu_l = (const float*)d_in[19];
    const float* b2_bu   = (const float*)d_in[20];
    const float* w2_bu_r = (const float*)d_in[21];
    const float* dec_w1  = (const float*)d_in[22];
    const float* dec_b1  = (const float*)d_in[23];
    const float* dec_w2  = (const float*)d_in[24];
    const float* dec_b2  = (const float*)d_in[25];

    int nu = in_sizes[0] / 3;
    int nb = in_sizes[1] / 384;
    int E  = in_sizes[2];
    int EL = in_sizes[4];
    float* out = (float*)d_out;

    float *u0, *b0, *u1, *b1, *u2, *b2, *mu, *mb;
    __half *u0h, *b0h, *u1h, *b1h, *uph, *bph;
    int *degu, *degb, *offu, *offb, *posu, *posb, *nbu, *nub, *cnts;
    cudaGetSymbolAddress((void**)&u0, g_u0);
    cudaGetSymbolAddress((void**)&b0, g_b0);
    cudaGetSymbolAddress((void**)&u1, g_u1);
    cudaGetSymbolAddress((void**)&b1, g_b1);
    cudaGetSymbolAddress((void**)&u2, g_u2);
    cudaGetSymbolAddress((void**)&b2, g_b2);
    cudaGetSymbolAddress((void**)&mu, g_mu);
    cudaGetSymbolAddress((void**)&mb, g_mb);
    cudaGetSymbolAddress((void**)&u0h, g_u0h);
    cudaGetSymbolAddress((void**)&b0h, g_b0h);
    cudaGetSymbolAddress((void**)&u1h, g_u1h);
    cudaGetSymbolAddress((void**)&b1h, g_b1h);
    cudaGetSymbolAddress((void**)&uph, g_uph);
    cudaGetSymbolAddress((void**)&bph, g_bph);
    cudaGetSymbolAddress((void**)&degu, g_deg_u);
    cudaGetSymbolAddress((void**)&degb, g_deg_b);
    cudaGetSymbolAddress((void**)&offu, g_off_u);
    cudaGetSymbolAddress((void**)&offb, g_off_b);
    cudaGetSymbolAddress((void**)&posu, g_pos_u);
    cudaGetSymbolAddress((void**)&posb, g_pos_b);
    cudaGetSymbolAddress((void**)&nbu, g_nbr_b_of_u);
    cudaGetSymbolAddress((void**)&nub, g_nbr_u_of_b);
    cudaGetSymbolAddress((void**)&cnts, g_counters);

    static const int BOOK_SMEM = (384 * 64 + 32 * 96) * 4;
    cudaFuncSetAttribute(book_proj_kernel, cudaFuncAttributeMaxDynamicSharedMemorySize, BOOK_SMEM);
    cudaFuncSetAttribute(sage_transform2_kernel<true, true>,
                         cudaFuncAttributeMaxDynamicSharedMemorySize, SAGE_T_SMEM);
    cudaFuncSetAttribute(sage_transform2_kernel<false, false>,
                         cudaFuncAttributeMaxDynamicSharedMemorySize, SAGE_T_SMEM);
    cudaFuncSetAttribute(dec_pre2_kernel, cudaFuncAttributeMaxDynamicSharedMemorySize, DEC_P_SMEM);

    // ---- CSR build ----
    zero_all_kernel<<<(nu + 255) / 256, 256>>>(degu, nu, degb, nb, cnts, 2);
    deg_pos_kernel<<<(E / 8 + 255) / 256, 256>>>(edge_src, edge_dst, degu, degb, posu, posb, E);
    int gu = (nu + 1023) / 1024, gb = (nb + 1023) / 1024;
    alloc_offsets2_kernel<<<gu + gb, 1024>>>(degu, offu, degb, offb, cnts, nu, nb, gu);
    scatter_pos_kernel<<<(E / 8 + 255) / 256, 256>>>(edge_src, edge_dst, offu, offb,
                                                     posu, posb, nbu, nub, E);

    // ---- input projections ----
    {
        unsigned t = (unsigned)nu * 16u;
        user_proj_kernel<<<(t + 255) / 256, 256>>>(user_x, user_lin_w, user_lin_b, u0, u0h, nu);
    }
    book_proj_kernel<<<296, 256, BOOK_SMEM>>>(book_x, book_lin_w, book_lin_b, b0, b0h, nb);

    // single-wave grids: gather 444 (3/SM), transform 444 (3/SM), dec_pre 592 (4/SM)
    // ---- layer 1 ----
    sage_gather2_kernel<<<444, 256>>>(u0h, offb, degb, nub, mb, nb,
                                      b0h, offu, degu, nbu, mu, nu, 222);
    sage_transform2_kernel<true, true><<<444, 256, SAGE_T_SMEM>>>(
        mb, b0, w1_ub_l, b1_ub, w1_ub_r, b1, b1h, nb,
        mu, u0, w1_bu_l, b1_bu, w1_bu_r, u1, u1h, nu, 148);

    // ---- layer 2 ----
    sage_gather2_kernel<<<444, 256>>>(u1h, offb, degb, nub, mb, nb,
                                      b1h, offu, degu, nbu, mu, nu, 222);
    sage_transform2_kernel<false, false><<<444, 256, SAGE_T_SMEM>>>(
        mb, b1, w2_ub_l, b2_ub, w2_ub_r, b2, nullptr, nb,
        mu, u1, w2_bu_l, b2_bu, w2_bu_r, u2, nullptr, nu, 148);

    // ---- decoder ----
    dec_pre2_kernel<<<592, 256, DEC_P_SMEM>>>(u2, dec_w1, dec_b1, uph, nu,
                                              b2, dec_w1 + 64 * 128, bph, nb, 396);
    dec_edge_kernel<<<1024, 256>>>(uph, bph, label_src, label_dst, dec_w2, dec_b2, out, EL);
}